// round 1
// baseline (speedup 1.0000x reference)
#include <cuda_runtime.h>
#include <math.h>

#define B_    2
#define S_    2048
#define H_    2048
#define NH_   16
#define HD_   128
#define M_    (B_*S_)       // 4096 rows
#define OQKV_ (3*H_)        // 6144

// Scratch (device globals: allowed; no runtime allocation)
__device__ float g_qkv [(size_t)M_ * OQKV_];   // ~100 MB
__device__ float g_attn[(size_t)M_ * H_];      // ~32 MB

// ---------------------------------------------------------------------------
// GEMM: C[M,N] = A[M,K] @ B[N,K]^T + bias[N]   (both operands K-contiguous)
// Block tile 64x64, K tile 16, 256 threads, 4x4 microtile per thread.
// ---------------------------------------------------------------------------
__global__ __launch_bounds__(256) void gemm_nt_bias(
    const float* __restrict__ A, const float* __restrict__ Bm,
    const float* __restrict__ bias, float* __restrict__ C,
    int Mdim, int Ndim, int Kdim)
{
    const int BM = 64, BN = 64, BK = 16;
    __shared__ float As[BK][BM + 4];   // row = 68 floats -> 16B-aligned rows
    __shared__ float Bs[BK][BN + 4];

    const int tid = threadIdx.x;
    const int tx  = tid & 15;
    const int ty  = tid >> 4;
    const int m0  = blockIdx.y * BM;
    const int n0  = blockIdx.x * BN;

    const int lk = tid & (BK - 1);   // 0..15
    const int lm = tid >> 4;         // 0..15

    float acc[4][4];
    #pragma unroll
    for (int i = 0; i < 4; i++)
        #pragma unroll
        for (int j = 0; j < 4; j++) acc[i][j] = 0.f;

    for (int k0 = 0; k0 < Kdim; k0 += BK) {
        #pragma unroll
        for (int i = 0; i < 4; i++) {
            As[lk][lm + 16*i] = A [(size_t)(m0 + lm + 16*i) * Kdim + k0 + lk];
            Bs[lk][lm + 16*i] = Bm[(size_t)(n0 + lm + 16*i) * Kdim + k0 + lk];
        }
        __syncthreads();
        #pragma unroll
        for (int k = 0; k < BK; k++) {
            float4 a4 = *reinterpret_cast<const float4*>(&As[k][ty * 4]);
            float4 b4 = *reinterpret_cast<const float4*>(&Bs[k][tx * 4]);
            float a[4] = {a4.x, a4.y, a4.z, a4.w};
            float b[4] = {b4.x, b4.y, b4.z, b4.w};
            #pragma unroll
            for (int i = 0; i < 4; i++)
                #pragma unroll
                for (int j = 0; j < 4; j++)
                    acc[i][j] = fmaf(a[i], b[j], acc[i][j]);
        }
        __syncthreads();
    }

    #pragma unroll
    for (int i = 0; i < 4; i++) {
        const size_t row = (size_t)(m0 + ty*4 + i) * Ndim + n0;
        #pragma unroll
        for (int j = 0; j < 4; j++)
            C[row + tx*4 + j] = acc[i][j] + bias[n0 + tx*4 + j];
    }
}

// ---------------------------------------------------------------------------
// Flash attention, fp32.  One block per (q-tile, head, batch).
// Br=Bc=64, HD=128.  256 threads.  Online softmax.  K/V share a smem buffer;
// V load (192 threads) overlaps the row-softmax pass (64 threads).
// ---------------------------------------------------------------------------
#define Br  64
#define Bc  64
#define HDP 132   // padded head-dim row stride (2-way conflicts max)
#define BcP 65

__global__ __launch_bounds__(256) void attn_kernel()
{
    extern __shared__ float sm[];
    float* sQ    = sm;                    // Br*HDP
    float* sKV   = sQ  + Br * HDP;        // Bc*HDP
    float* sS    = sKV + Bc * HDP;        // Br*BcP
    float* sMax  = sS  + Br * BcP;        // Br
    float* sSum  = sMax + Br;             // Br
    float* sCorr = sSum + Br;             // Br

    const int qt = blockIdx.x;            // 0..31
    const int h  = blockIdx.y;            // 0..15
    const int b  = blockIdx.z;            // 0..1
    const int t  = threadIdx.x;

    const float scale = 0.08838834764831844f;  // 1/sqrt(128)

    const float* qbase = g_qkv + (size_t)(b * S_ + qt * Br) * OQKV_ +            h * HD_;
    const float* kbase = g_qkv + (size_t)(b * S_)           * OQKV_ +    H_ +    h * HD_;
    const float* vbase = g_qkv + (size_t)(b * S_)           * OQKV_ +  2*H_ +    h * HD_;

    // Load Q tile
    for (int idx = t; idx < Br * HD_; idx += 256) {
        int r = idx >> 7, d = idx & 127;
        sQ[r * HDP + d] = qbase[(size_t)r * OQKV_ + d];
    }
    if (t < Br) { sMax[t] = -INFINITY; sSum[t] = 0.f; }

    float acc[4][8];
    #pragma unroll
    for (int i = 0; i < 4; i++)
        #pragma unroll
        for (int j = 0; j < 8; j++) acc[i][j] = 0.f;

    const int ty = t >> 4, tx = t & 15;   // 16x16 for S-phase
    __syncthreads();

    for (int kt = 0; kt < S_ / Bc; kt++) {
        // ---- load K tile
        for (int idx = t; idx < Bc * HD_; idx += 256) {
            int r = idx >> 7, d = idx & 127;
            sKV[r * HDP + d] = kbase[(size_t)(kt * Bc + r) * OQKV_ + d];
        }
        __syncthreads();

        // ---- S = Q @ K^T  (each thread 4x4 of a 64x64 tile)
        {
            float s[4][4];
            #pragma unroll
            for (int i = 0; i < 4; i++)
                #pragma unroll
                for (int j = 0; j < 4; j++) s[i][j] = 0.f;
            for (int d = 0; d < HD_; d++) {
                float a[4], bb[4];
                #pragma unroll
                for (int i = 0; i < 4; i++) a[i]  = sQ [(ty*4 + i) * HDP + d];
                #pragma unroll
                for (int j = 0; j < 4; j++) bb[j] = sKV[(tx*4 + j) * HDP + d];
                #pragma unroll
                for (int i = 0; i < 4; i++)
                    #pragma unroll
                    for (int j = 0; j < 4; j++)
                        s[i][j] = fmaf(a[i], bb[j], s[i][j]);
            }
            #pragma unroll
            for (int i = 0; i < 4; i++)
                #pragma unroll
                for (int j = 0; j < 4; j++)
                    sS[(ty*4 + i) * BcP + tx*4 + j] = s[i][j];
        }
        __syncthreads();

        // ---- online softmax (threads 0..63) overlapped with V load (64..255)
        if (t < Br) {
            const int r = t;
            float mold = sMax[r];
            float mnew = mold;
            for (int c = 0; c < Bc; c++)
                mnew = fmaxf(mnew, sS[r * BcP + c] * scale);
            float corr = __expf(mold - mnew);    // exp(-inf)=0 on first tile
            float sum = 0.f;
            for (int c = 0; c < Bc; c++) {
                float p = __expf(sS[r * BcP + c] * scale - mnew);
                sS[r * BcP + c] = p;
                sum += p;
            }
            sSum[r]  = sSum[r] * corr + sum;
            sMax[r]  = mnew;
            sCorr[r] = corr;
        } else {
            for (int idx = t - 64; idx < Bc * HD_; idx += 192) {
                int r = idx >> 7, d = idx & 127;
                sKV[r * HDP + d] = vbase[(size_t)(kt * Bc + r) * OQKV_ + d];
            }
        }
        __syncthreads();

        // ---- O = O*corr + P @ V   (each thread 4 rows x 8 cols of 64x128)
        {
            #pragma unroll
            for (int i = 0; i < 4; i++) {
                float corr = sCorr[ty*4 + i];
                #pragma unroll
                for (int j = 0; j < 8; j++) acc[i][j] *= corr;
            }
            for (int k = 0; k < Bc; k++) {
                float p[4], v[8];
                #pragma unroll
                for (int i = 0; i < 4; i++) p[i] = sS[(ty*4 + i) * BcP + k];
                #pragma unroll
                for (int j = 0; j < 8; j++) v[j] = sKV[k * HDP + tx*8 + j];
                #pragma unroll
                for (int i = 0; i < 4; i++)
                    #pragma unroll
                    for (int j = 0; j < 8; j++)
                        acc[i][j] = fmaf(p[i], v[j], acc[i][j]);
            }
        }
        __syncthreads();
    }

    // ---- normalize and write to g_attn in [b, s, nh*hd] layout
    #pragma unroll
    for (int i = 0; i < 4; i++) {
        const int r = ty*4 + i;
        const float inv = 1.f / sSum[r];
        const size_t row = (size_t)(b * S_ + qt * Br + r) * H_ + h * HD_;
        #pragma unroll
        for (int j = 0; j < 8; j++)
            g_attn[row + tx*8 + j] = acc[i][j] * inv;
    }
}

// ---------------------------------------------------------------------------
extern "C" void kernel_launch(void* const* d_in, const int* in_sizes, int n_in,
                              void* d_out, int out_size)
{
    const float* x     = (const float*)d_in[0];
    const float* w_qkv = (const float*)d_in[1];
    const float* b_qkv = (const float*)d_in[2];
    const float* w_out = (const float*)d_in[3];
    const float* b_out = (const float*)d_in[4];
    float* out = (float*)d_out;

    float* qkv_ptr;
    float* attn_ptr;
    cudaGetSymbolAddress((void**)&qkv_ptr,  g_qkv);
    cudaGetSymbolAddress((void**)&attn_ptr, g_attn);

    const int attn_smem = (Br*HDP + Bc*HDP + Br*BcP + 3*Br) * (int)sizeof(float);
    cudaFuncSetAttribute(attn_kernel,
                         cudaFuncAttributeMaxDynamicSharedMemorySize, attn_smem);

    // 1) QKV projection: [4096,6144] = x[4096,2048] @ w_qkv[6144,2048]^T + b
    gemm_nt_bias<<<dim3(OQKV_/64, M_/64), 256>>>(x, w_qkv, b_qkv, qkv_ptr,
                                                 M_, OQKV_, H_);
    // 2) Attention
    attn_kernel<<<dim3(S_/Br, NH_, B_), 256, attn_smem>>>();

    // 3) Output projection: [4096,2048] = attn[4096,2048] @ w_out[2048,2048]^T + b
    gemm_nt_bias<<<dim3(H_/64, M_/64), 256>>>(attn_ptr, w_out, b_out, out,
                                              M_, H_, H_);
}

// round 4
// speedup vs baseline: 2.4186x; 2.4186x over previous
#include <cuda_runtime.h>
#include <cuda_bf16.h>
#include <math.h>
#include <stdint.h>
#include <cstdint>
#include <cstddef>

#define B_    2
#define S_    2048
#define H_    2048
#define NH_   16
#define HD_   128
#define M_    (B_*S_)       // 4096
#define OQKV_ (3*H_)        // 6144

// ---------------------------------------------------------------------------
// Device-global scratch
// ---------------------------------------------------------------------------
__device__ float g_qkv [(size_t)M_ * OQKV_];
__device__ float g_attn[(size_t)M_ * H_];

__device__ __nv_bfloat16 g_xh [(size_t)M_ * H_];
__device__ __nv_bfloat16 g_xl [(size_t)M_ * H_];
__device__ __nv_bfloat16 g_wqh[(size_t)OQKV_ * H_];
__device__ __nv_bfloat16 g_wql[(size_t)OQKV_ * H_];
__device__ __nv_bfloat16 g_woh[(size_t)H_ * H_];
__device__ __nv_bfloat16 g_wol[(size_t)H_ * H_];
__device__ __nv_bfloat16 g_ath[(size_t)M_ * H_];
__device__ __nv_bfloat16 g_atl[(size_t)M_ * H_];

// ---------------------------------------------------------------------------
// helpers
// ---------------------------------------------------------------------------
__device__ __forceinline__ uint32_t smem_u32(const void* p) {
    uint32_t a;
    asm("{ .reg .u64 t; cvta.to.shared.u64 t, %1; cvt.u32.u64 %0, t; }"
        : "=r"(a) : "l"(p));
    return a;
}
__device__ __forceinline__ void ldsm_x4(uint32_t* r, uint32_t addr) {
    asm volatile("ldmatrix.sync.aligned.m8n8.x4.shared.b16 {%0,%1,%2,%3}, [%4];"
                 : "=r"(r[0]), "=r"(r[1]), "=r"(r[2]), "=r"(r[3]) : "r"(addr));
}
__device__ __forceinline__ void ldsm_x2(uint32_t* r, uint32_t addr) {
    asm volatile("ldmatrix.sync.aligned.m8n8.x2.shared.b16 {%0,%1}, [%2];"
                 : "=r"(r[0]), "=r"(r[1]) : "r"(addr));
}
__device__ __forceinline__ void mma_bf16(float* c, const uint32_t* a, const uint32_t* b) {
    asm volatile(
        "mma.sync.aligned.m16n8k16.row.col.f32.bf16.bf16.f32 "
        "{%0,%1,%2,%3}, {%4,%5,%6,%7}, {%8,%9}, {%0,%1,%2,%3};"
        : "+f"(c[0]), "+f"(c[1]), "+f"(c[2]), "+f"(c[3])
        : "r"(a[0]), "r"(a[1]), "r"(a[2]), "r"(a[3]), "r"(b[0]), "r"(b[1]));
}
__device__ __forceinline__ void cp16(uint32_t saddr, const void* gptr) {
    asm volatile("cp.async.cg.shared.global [%0], [%1], 16;"
                 :: "r"(saddr), "l"(__cvta_generic_to_global(gptr)));
}
#define CP_COMMIT() asm volatile("cp.async.commit_group;" ::: "memory")
#define CP_WAIT1()  asm volatile("cp.async.wait_group 1;" ::: "memory")
#define CP_WAIT0()  asm volatile("cp.async.wait_group 0;" ::: "memory")

// ---------------------------------------------------------------------------
// fp32 -> bf16 hi/lo split
// ---------------------------------------------------------------------------
__global__ __launch_bounds__(256) void conv_hilo(
    const float* __restrict__ s, __nv_bfloat16* __restrict__ hi,
    __nv_bfloat16* __restrict__ lo, int n)
{
    int i = (blockIdx.x * 256 + threadIdx.x) * 4;
    if (i >= n) return;
    float4 v = *(const float4*)(s + i);
    __nv_bfloat16 h0 = __float2bfloat16(v.x);
    __nv_bfloat16 h1 = __float2bfloat16(v.y);
    __nv_bfloat16 h2 = __float2bfloat16(v.z);
    __nv_bfloat16 h3 = __float2bfloat16(v.w);
    float l0 = v.x - __bfloat162float(h0);
    float l1 = v.y - __bfloat162float(h1);
    float l2 = v.z - __bfloat162float(h2);
    float l3 = v.w - __bfloat162float(h3);
    *(__nv_bfloat162*)(hi + i)     = __nv_bfloat162(h0, h1);
    *(__nv_bfloat162*)(hi + i + 2) = __nv_bfloat162(h2, h3);
    *(__nv_bfloat162*)(lo + i)     = __floats2bfloat162_rn(l0, l1);
    *(__nv_bfloat162*)(lo + i + 2) = __floats2bfloat162_rn(l2, l3);
}

// ---------------------------------------------------------------------------
// mma.sync GEMM:  C[M,N] = A[M,K] @ B[N,K]^T + bias  (3-term bf16 hi/lo)
// 128x128 block tile, BK=32, 8 warps (warp tile 64x32), cp.async 2-stage.
// smem: per stage 4 matrices (Ah, Al, Bh, Bl) of 128 rows x 40 bf16 (80B).
// ---------------------------------------------------------------------------
#define BK    32
#define SA    40
#define ROWB  (SA * 2)              // 80 bytes per smem row
#define MATB  (128 * ROWB)          // 10240
#define STAGEB (4 * MATB)           // 40960
#define GEMM_SMEM (2 * STAGEB)      // 81920

__device__ __forceinline__ void stage_load(
    uint32_t s0, const __nv_bfloat16* __restrict__ Ah,
    const __nv_bfloat16* __restrict__ Al,
    const __nv_bfloat16* __restrict__ Bh,
    const __nv_bfloat16* __restrict__ Bl,
    int m0, int n0, int Kdim, int kb, int t)
{
    const size_t kof = (size_t)kb * BK;
    #pragma unroll
    for (int c = t; c < 512; c += 256) {
        int row = c >> 2, cc = c & 3;
        uint32_t so = (uint32_t)(row * ROWB + cc * 16);
        size_t ga = (size_t)(m0 + row) * Kdim + kof + cc * 8;
        size_t gb = (size_t)(n0 + row) * Kdim + kof + cc * 8;
        cp16(s0 + 0 * MATB + so, Ah + ga);
        cp16(s0 + 1 * MATB + so, Al + ga);
        cp16(s0 + 2 * MATB + so, Bh + gb);
        cp16(s0 + 3 * MATB + so, Bl + gb);
    }
}

__global__ __launch_bounds__(256, 1) void gemm_mma(
    const __nv_bfloat16* __restrict__ Ah, const __nv_bfloat16* __restrict__ Al,
    const __nv_bfloat16* __restrict__ Bh, const __nv_bfloat16* __restrict__ Bl,
    const float* __restrict__ bias, float* __restrict__ C,
    int Ndim, int Kdim)
{
    extern __shared__ char smc[];
    const uint32_t sb = smem_u32(smc);

    const int t    = threadIdx.x;
    const int lane = t & 31;
    const int wid  = t >> 5;
    const int wm   = wid >> 2;        // 0..1
    const int wn   = wid & 3;         // 0..3
    const int m0   = blockIdx.y * 128;
    const int n0   = blockIdx.x * 128;

    float acc[4][4][4];
    #pragma unroll
    for (int i = 0; i < 4; i++)
        #pragma unroll
        for (int j = 0; j < 4; j++)
            #pragma unroll
            for (int k = 0; k < 4; k++) acc[i][j][k] = 0.f;

    const int nkb = Kdim / BK;

    stage_load(sb, Ah, Al, Bh, Bl, m0, n0, Kdim, 0, t);
    CP_COMMIT();

    // ldmatrix lane address components
    const int ra  = lane & 15;          // A row within 16
    const int ca  = (lane >> 4) & 1;    // A col-quadrant (0/1 -> +0/+8)
    const int rb  = lane & 7;           // B row (n) within 8
    const int cb  = (lane >> 3) & 1;    // B col-quadrant

    for (int kb = 0; kb < nkb; kb++) {
        const int cur = kb & 1;
        if (kb + 1 < nkb) {
            stage_load(sb + (cur ^ 1) * STAGEB, Ah, Al, Bh, Bl, m0, n0, Kdim, kb + 1, t);
            CP_COMMIT();
            CP_WAIT1();
        } else {
            CP_WAIT0();
        }
        __syncthreads();

        const uint32_t s0 = sb + cur * STAGEB;
        #pragma unroll
        for (int ks = 0; ks < 2; ks++) {
            const int k0 = ks * 16;
            uint32_t ah[4][4], al[4][4], bh[4][2], bl[4][2];
            const uint32_t aoff = (uint32_t)((wm * 64 + ra) * ROWB + (k0 + ca * 8) * 2);
            #pragma unroll
            for (int mf = 0; mf < 4; mf++) {
                ldsm_x4(ah[mf], s0 + 0 * MATB + aoff + (uint32_t)(mf * 16 * ROWB));
                ldsm_x4(al[mf], s0 + 1 * MATB + aoff + (uint32_t)(mf * 16 * ROWB));
            }
            const uint32_t boff = (uint32_t)((wn * 32 + rb) * ROWB + (k0 + cb * 8) * 2);
            #pragma unroll
            for (int nf = 0; nf < 4; nf++) {
                ldsm_x2(bh[nf], s0 + 2 * MATB + boff + (uint32_t)(nf * 8 * ROWB));
                ldsm_x2(bl[nf], s0 + 3 * MATB + boff + (uint32_t)(nf * 8 * ROWB));
            }
            #pragma unroll
            for (int mf = 0; mf < 4; mf++)
                #pragma unroll
                for (int nf = 0; nf < 4; nf++) {
                    mma_bf16(acc[mf][nf], ah[mf], bh[nf]);
                    mma_bf16(acc[mf][nf], ah[mf], bl[nf]);
                    mma_bf16(acc[mf][nf], al[mf], bh[nf]);
                }
        }
        __syncthreads();
    }

    // epilogue
    const int gid = lane >> 2, qid = lane & 3;
    #pragma unroll
    for (int mf = 0; mf < 4; mf++) {
        const int row0 = m0 + wm * 64 + mf * 16 + gid;
        #pragma unroll
        for (int nf = 0; nf < 4; nf++) {
            const int col = n0 + wn * 32 + nf * 8 + qid * 2;
            const float b0 = bias[col], b1 = bias[col + 1];
            float2 v0 = make_float2(acc[mf][nf][0] + b0, acc[mf][nf][1] + b1);
            float2 v1 = make_float2(acc[mf][nf][2] + b0, acc[mf][nf][3] + b1);
            *(float2*)(C + (size_t)row0 * Ndim + col)       = v0;
            *(float2*)(C + (size_t)(row0 + 8) * Ndim + col) = v1;
        }
    }
}

// ---------------------------------------------------------------------------
// Flash attention, fp32 SIMT. Br=Bc=64, HD=128, 256 threads.
// ---------------------------------------------------------------------------
#define Br  64
#define Bc  64
#define QTS 68
#define VST 132
#define SST 65
#define ATTN_SMEM ((128*QTS + 128*QTS + Br*SST + 3*Br) * 4)

__global__ __launch_bounds__(256) void attn_kernel()
{
    extern __shared__ float sm[];
    float* sQt  = sm;
    float* sKV  = sQt + 128 * QTS;
    float* sS   = sKV + 128 * QTS;
    float* sMax = sS + Br * SST;
    float* sSum = sMax + Br;
    float* sCorr = sSum + Br;

    const int qt = blockIdx.x;
    const int h  = blockIdx.y;
    const int b  = blockIdx.z;
    const int t  = threadIdx.x;
    const float scale = 0.08838834764831844f;

    const float* qbase = g_qkv + (size_t)(b * S_ + qt * Br) * OQKV_ +          h * HD_;
    const float* kbase = g_qkv + (size_t)(b * S_)           * OQKV_ +   H_ +   h * HD_;
    const float* vbase = g_qkv + (size_t)(b * S_)           * OQKV_ + 2*H_ +   h * HD_;

    for (int idx = t; idx < 64 * 32; idx += 256) {
        int r  = idx & 63;
        int d0 = (idx >> 6) << 2;
        float4 q4 = *(const float4*)(qbase + (size_t)r * OQKV_ + d0);
        sQt[(d0 + 0) * QTS + r] = q4.x * scale;
        sQt[(d0 + 1) * QTS + r] = q4.y * scale;
        sQt[(d0 + 2) * QTS + r] = q4.z * scale;
        sQt[(d0 + 3) * QTS + r] = q4.w * scale;
    }
    if (t < Br) { sMax[t] = -INFINITY; sSum[t] = 0.f; }

    float acc[4][8];
    #pragma unroll
    for (int i = 0; i < 4; i++)
        #pragma unroll
        for (int j = 0; j < 8; j++) acc[i][j] = 0.f;

    const int ty = t >> 4, tx = t & 15;
    __syncthreads();

    for (int kt = 0; kt < S_ / Bc; kt++) {
        for (int idx = t; idx < 64 * 32; idx += 256) {
            int c  = idx & 63;
            int d0 = (idx >> 6) << 2;
            float4 k4 = *(const float4*)(kbase + (size_t)(kt * Bc + c) * OQKV_ + d0);
            sKV[(d0 + 0) * QTS + c] = k4.x;
            sKV[(d0 + 1) * QTS + c] = k4.y;
            sKV[(d0 + 2) * QTS + c] = k4.z;
            sKV[(d0 + 3) * QTS + c] = k4.w;
        }
        __syncthreads();

        {
            float s[4][4];
            #pragma unroll
            for (int i = 0; i < 4; i++)
                #pragma unroll
                for (int j = 0; j < 4; j++) s[i][j] = 0.f;
            #pragma unroll 4
            for (int d = 0; d < HD_; d++) {
                float4 a4 = *(const float4*)&sQt[d * QTS + ty * 4];
                float4 b4 = *(const float4*)&sKV[d * QTS + tx * 4];
                float a[4] = {a4.x, a4.y, a4.z, a4.w};
                float bb[4] = {b4.x, b4.y, b4.z, b4.w};
                #pragma unroll
                for (int i = 0; i < 4; i++)
                    #pragma unroll
                    for (int j = 0; j < 4; j++)
                        s[i][j] = fmaf(a[i], bb[j], s[i][j]);
            }
            #pragma unroll
            for (int i = 0; i < 4; i++)
                #pragma unroll
                for (int j = 0; j < 4; j++)
                    sS[(ty * 4 + i) * SST + tx * 4 + j] = s[i][j];
        }
        __syncthreads();

        if (t < Br) {
            const int r = t;
            float mold = sMax[r];
            float mnew = mold;
            #pragma unroll 4
            for (int c = 0; c < Bc; c++)
                mnew = fmaxf(mnew, sS[r * SST + c]);
            float corr = __expf(mold - mnew);
            float sum = 0.f;
            #pragma unroll 4
            for (int c = 0; c < Bc; c++) {
                float p = __expf(sS[r * SST + c] - mnew);
                sS[r * SST + c] = p;
                sum += p;
            }
            sSum[r]  = sSum[r] * corr + sum;
            sMax[r]  = mnew;
            sCorr[r] = corr;
        } else {
            for (int idx = t - 64; idx < 64 * 32; idx += 192) {
                int r  = idx >> 5;
                int c4 = (idx & 31) << 2;
                *(float4*)&sKV[r * VST + c4] =
                    *(const float4*)(vbase + (size_t)(kt * Bc + r) * OQKV_ + c4);
            }
        }
        __syncthreads();

        {
            #pragma unroll
            for (int i = 0; i < 4; i++) {
                float corr = sCorr[ty * 4 + i];
                #pragma unroll
                for (int j = 0; j < 8; j++) acc[i][j] *= corr;
            }
            #pragma unroll 2
            for (int k = 0; k < Bc; k++) {
                float p[4];
                #pragma unroll
                for (int i = 0; i < 4; i++) p[i] = sS[(ty * 4 + i) * SST + k];
                float4 v0 = *(const float4*)&sKV[k * VST + tx * 8];
                float4 v1 = *(const float4*)&sKV[k * VST + tx * 8 + 4];
                float v[8] = {v0.x, v0.y, v0.z, v0.w, v1.x, v1.y, v1.z, v1.w};
                #pragma unroll
                for (int i = 0; i < 4; i++)
                    #pragma unroll
                    for (int j = 0; j < 8; j++)
                        acc[i][j] = fmaf(p[i], v[j], acc[i][j]);
            }
        }
        __syncthreads();
    }

    #pragma unroll
    for (int i = 0; i < 4; i++) {
        const int r = ty * 4 + i;
        const float inv = 1.f / sSum[r];
        float* orow = g_attn + (size_t)(b * S_ + qt * Br + r) * H_ + h * HD_ + tx * 8;
        float4 o0, o1;
        o0.x = acc[i][0] * inv; o0.y = acc[i][1] * inv;
        o0.z = acc[i][2] * inv; o0.w = acc[i][3] * inv;
        o1.x = acc[i][4] * inv; o1.y = acc[i][5] * inv;
        o1.z = acc[i][6] * inv; o1.w = acc[i][7] * inv;
        *(float4*)(orow)     = o0;
        *(float4*)(orow + 4) = o1;
    }
}

// ---------------------------------------------------------------------------
extern "C" void kernel_launch(void* const* d_in, const int* in_sizes, int n_in,
                              void* d_out, int out_size)
{
    const float* x     = (const float*)d_in[0];
    const float* w_qkv = (const float*)d_in[1];
    const float* b_qkv = (const float*)d_in[2];
    const float* w_out = (const float*)d_in[3];
    const float* b_out = (const float*)d_in[4];
    float* out = (float*)d_out;

    float *qkv_p, *attn_p;
    __nv_bfloat16 *xh, *xl, *wqh, *wql, *woh, *wol, *ath, *atl;
    cudaGetSymbolAddress((void**)&qkv_p,  g_qkv);
    cudaGetSymbolAddress((void**)&attn_p, g_attn);
    cudaGetSymbolAddress((void**)&xh,  g_xh);   cudaGetSymbolAddress((void**)&xl,  g_xl);
    cudaGetSymbolAddress((void**)&wqh, g_wqh);  cudaGetSymbolAddress((void**)&wql, g_wql);
    cudaGetSymbolAddress((void**)&woh, g_woh);  cudaGetSymbolAddress((void**)&wol, g_wol);
    cudaGetSymbolAddress((void**)&ath, g_ath);  cudaGetSymbolAddress((void**)&atl, g_atl);

    cudaFuncSetAttribute(gemm_mma, cudaFuncAttributeMaxDynamicSharedMemorySize, GEMM_SMEM);
    cudaFuncSetAttribute(attn_kernel, cudaFuncAttributeMaxDynamicSharedMemorySize, ATTN_SMEM);

    const int nx = M_ * H_, nwq = OQKV_ * H_, nwo = H_ * H_;
    conv_hilo<<<(nx  / 4 + 255) / 256, 256>>>(x,     xh,  xl,  nx);
    conv_hilo<<<(nwq / 4 + 255) / 256, 256>>>(w_qkv, wqh, wql, nwq);
    conv_hilo<<<(nwo / 4 + 255) / 256, 256>>>(w_out, woh, wol, nwo);

    // 1) QKV projection (HMMA)
    gemm_mma<<<dim3(OQKV_ / 128, M_ / 128), 256, GEMM_SMEM>>>(
        xh, xl, wqh, wql, b_qkv, qkv_p, OQKV_, H_);

    // 2) Attention
    attn_kernel<<<dim3(S_ / Br, NH_, B_), 256, ATTN_SMEM>>>();

    // 3) attn -> hi/lo, out projection (HMMA)
    conv_hilo<<<(nx / 4 + 255) / 256, 256>>>(attn_p, ath, atl, nx);
    gemm_mma<<<dim3(H_ / 128, M_ / 128), 256, GEMM_SMEM>>>(
        ath, atl, woh, wol, b_out, out, H_, H_);
}

// round 5
// speedup vs baseline: 4.9902x; 2.0632x over previous
#include <cuda_runtime.h>
#include <cuda_bf16.h>
#include <math.h>
#include <stdint.h>
#include <cstdint>
#include <cstddef>

#define B_    2
#define S_    2048
#define H_    2048
#define NH_   16
#define HD_   128
#define M_    (B_*S_)       // 4096
#define OQKV_ (3*H_)        // 6144

// ---------------------------------------------------------------------------
// Device-global scratch
// ---------------------------------------------------------------------------
__device__ __nv_bfloat16 g_xh  [(size_t)M_ * H_];
__device__ __nv_bfloat16 g_xl  [(size_t)M_ * H_];
__device__ __nv_bfloat16 g_wqh [(size_t)OQKV_ * H_];
__device__ __nv_bfloat16 g_wql [(size_t)OQKV_ * H_];
__device__ __nv_bfloat16 g_woh [(size_t)H_ * H_];
__device__ __nv_bfloat16 g_wol [(size_t)H_ * H_];
__device__ __nv_bfloat16 g_qkvh[(size_t)M_ * OQKV_];
__device__ __nv_bfloat16 g_qkvl[(size_t)M_ * OQKV_];
__device__ __nv_bfloat16 g_ath [(size_t)M_ * H_];
__device__ __nv_bfloat16 g_atl [(size_t)M_ * H_];

// ---------------------------------------------------------------------------
// helpers
// ---------------------------------------------------------------------------
__device__ __forceinline__ uint32_t smem_u32(const void* p) {
    uint32_t a;
    asm("{ .reg .u64 t; cvta.to.shared.u64 t, %1; cvt.u32.u64 %0, t; }"
        : "=r"(a) : "l"(p));
    return a;
}
__device__ __forceinline__ void ldsm_x4(uint32_t* r, uint32_t addr) {
    asm volatile("ldmatrix.sync.aligned.m8n8.x4.shared.b16 {%0,%1,%2,%3}, [%4];"
                 : "=r"(r[0]), "=r"(r[1]), "=r"(r[2]), "=r"(r[3]) : "r"(addr));
}
__device__ __forceinline__ void ldsm_x4t(uint32_t* r, uint32_t addr) {
    asm volatile("ldmatrix.sync.aligned.m8n8.x4.trans.shared.b16 {%0,%1,%2,%3}, [%4];"
                 : "=r"(r[0]), "=r"(r[1]), "=r"(r[2]), "=r"(r[3]) : "r"(addr));
}
__device__ __forceinline__ void ldsm_x2(uint32_t* r, uint32_t addr) {
    asm volatile("ldmatrix.sync.aligned.m8n8.x2.shared.b16 {%0,%1}, [%2];"
                 : "=r"(r[0]), "=r"(r[1]) : "r"(addr));
}
__device__ __forceinline__ void mma_bf16(float* c, const uint32_t* a, const uint32_t* b) {
    asm volatile(
        "mma.sync.aligned.m16n8k16.row.col.f32.bf16.bf16.f32 "
        "{%0,%1,%2,%3}, {%4,%5,%6,%7}, {%8,%9}, {%0,%1,%2,%3};"
        : "+f"(c[0]), "+f"(c[1]), "+f"(c[2]), "+f"(c[3])
        : "r"(a[0]), "r"(a[1]), "r"(a[2]), "r"(a[3]), "r"(b[0]), "r"(b[1]));
}
__device__ __forceinline__ void cp16(uint32_t saddr, const void* gptr) {
    asm volatile("cp.async.cg.shared.global [%0], [%1], 16;"
                 :: "r"(saddr), "l"(__cvta_generic_to_global(gptr)));
}
#define CP_COMMIT() asm volatile("cp.async.commit_group;" ::: "memory")
#define CP_WAIT1()  asm volatile("cp.async.wait_group 1;" ::: "memory")
#define CP_WAIT0()  asm volatile("cp.async.wait_group 0;" ::: "memory")

// pack two fp32 -> bf16x2 (lo in lower half, hi in upper half)
__device__ __forceinline__ uint32_t pack_bf16(float lo, float hi) {
    uint32_t r;
    asm("cvt.rn.bf16x2.f32 %0, %1, %2;" : "=r"(r) : "f"(hi), "f"(lo));
    return r;
}

// fast exp2 via degree-5 FMA polynomial (avoids MUFU bottleneck)
__device__ __forceinline__ float fexp2(float t) {
    t = fmaxf(t, -126.f);
    int   e = __float2int_rn(t);
    float f = t - (float)e;
    float p = 1.3333558146428443e-3f;
    p = fmaf(p, f, 9.618129107628477e-3f);
    p = fmaf(p, f, 5.550410866482158e-2f);
    p = fmaf(p, f, 2.402265069591007e-1f);
    p = fmaf(p, f, 6.931471805599453e-1f);
    p = fmaf(p, f, 1.0f);
    return p * __int_as_float((e + 127) << 23);
}

// ---------------------------------------------------------------------------
// fp32 -> bf16 hi/lo split (inputs only)
// ---------------------------------------------------------------------------
__global__ __launch_bounds__(256) void conv_hilo(
    const float* __restrict__ s, __nv_bfloat16* __restrict__ hi,
    __nv_bfloat16* __restrict__ lo, int n)
{
    int i = (blockIdx.x * 256 + threadIdx.x) * 4;
    if (i >= n) return;
    float4 v = *(const float4*)(s + i);
    uint32_t h01 = pack_bf16(v.x, v.y);
    uint32_t h23 = pack_bf16(v.z, v.w);
    float f0 = __uint_as_float(h01 << 16);
    float f1 = __uint_as_float(h01 & 0xFFFF0000u);
    float f2 = __uint_as_float(h23 << 16);
    float f3 = __uint_as_float(h23 & 0xFFFF0000u);
    *(uint32_t*)(hi + i)     = h01;
    *(uint32_t*)(hi + i + 2) = h23;
    *(uint32_t*)(lo + i)     = pack_bf16(v.x - f0, v.y - f1);
    *(uint32_t*)(lo + i + 2) = pack_bf16(v.z - f2, v.w - f3);
}

// ---------------------------------------------------------------------------
// mma.sync GEMM:  C[M,N] = A[M,K] @ B[N,K]^T + bias  (3-term bf16 hi/lo)
// 128x128 block tile, BK=32, 8 warps, cp.async 2-stage, 2 CTAs/SM.
// mode 0: fp32 output; mode 1: bf16 hi/lo output.
// ---------------------------------------------------------------------------
#define BK    32
#define SA    40
#define ROWB  (SA * 2)              // 80 bytes per smem row
#define MATB  (128 * ROWB)          // 10240
#define STAGEB (4 * MATB)           // 40960
#define GEMM_SMEM (2 * STAGEB)      // 81920

__device__ __forceinline__ void stage_load(
    uint32_t s0, const __nv_bfloat16* __restrict__ Ah,
    const __nv_bfloat16* __restrict__ Al,
    const __nv_bfloat16* __restrict__ Bh,
    const __nv_bfloat16* __restrict__ Bl,
    int m0, int n0, int Kdim, int kb, int t)
{
    const size_t kof = (size_t)kb * BK;
    #pragma unroll
    for (int c = t; c < 512; c += 256) {
        int row = c >> 2, cc = c & 3;
        uint32_t so = (uint32_t)(row * ROWB + cc * 16);
        size_t ga = (size_t)(m0 + row) * Kdim + kof + cc * 8;
        size_t gb = (size_t)(n0 + row) * Kdim + kof + cc * 8;
        cp16(s0 + 0 * MATB + so, Ah + ga);
        cp16(s0 + 1 * MATB + so, Al + ga);
        cp16(s0 + 2 * MATB + so, Bh + gb);
        cp16(s0 + 3 * MATB + so, Bl + gb);
    }
}

__global__ __launch_bounds__(256, 2) void gemm_mma(
    const __nv_bfloat16* __restrict__ Ah, const __nv_bfloat16* __restrict__ Al,
    const __nv_bfloat16* __restrict__ Bh, const __nv_bfloat16* __restrict__ Bl,
    const float* __restrict__ bias, float* __restrict__ Cf,
    __nv_bfloat16* __restrict__ Chi, __nv_bfloat16* __restrict__ Clo,
    int Ndim, int Kdim, int mode)
{
    extern __shared__ char smc[];
    const uint32_t sb = smem_u32(smc);

    const int t    = threadIdx.x;
    const int lane = t & 31;
    const int wid  = t >> 5;
    const int wm   = wid >> 2;
    const int wn   = wid & 3;
    const int m0   = blockIdx.y * 128;
    const int n0   = blockIdx.x * 128;

    float acc[4][4][4];
    #pragma unroll
    for (int i = 0; i < 4; i++)
        #pragma unroll
        for (int j = 0; j < 4; j++)
            #pragma unroll
            for (int k = 0; k < 4; k++) acc[i][j][k] = 0.f;

    const int nkb = Kdim / BK;

    stage_load(sb, Ah, Al, Bh, Bl, m0, n0, Kdim, 0, t);
    CP_COMMIT();

    const int ra  = lane & 15;
    const int ca  = (lane >> 4) & 1;
    const int rb  = lane & 7;
    const int cb  = (lane >> 3) & 1;

    for (int kb = 0; kb < nkb; kb++) {
        const int cur = kb & 1;
        if (kb + 1 < nkb) {
            stage_load(sb + (cur ^ 1) * STAGEB, Ah, Al, Bh, Bl, m0, n0, Kdim, kb + 1, t);
            CP_COMMIT();
            CP_WAIT1();
        } else {
            CP_WAIT0();
        }
        __syncthreads();

        const uint32_t s0 = sb + cur * STAGEB;
        #pragma unroll
        for (int ks = 0; ks < 2; ks++) {
            const int k0 = ks * 16;
            uint32_t ah[4][4], al[4][4], bh[4][2], bl[4][2];
            const uint32_t aoff = (uint32_t)((wm * 64 + ra) * ROWB + (k0 + ca * 8) * 2);
            #pragma unroll
            for (int mf = 0; mf < 4; mf++) {
                ldsm_x4(ah[mf], s0 + 0 * MATB + aoff + (uint32_t)(mf * 16 * ROWB));
                ldsm_x4(al[mf], s0 + 1 * MATB + aoff + (uint32_t)(mf * 16 * ROWB));
            }
            const uint32_t boff = (uint32_t)((wn * 32 + rb) * ROWB + (k0 + cb * 8) * 2);
            #pragma unroll
            for (int nf = 0; nf < 4; nf++) {
                ldsm_x2(bh[nf], s0 + 2 * MATB + boff + (uint32_t)(nf * 8 * ROWB));
                ldsm_x2(bl[nf], s0 + 3 * MATB + boff + (uint32_t)(nf * 8 * ROWB));
            }
            #pragma unroll
            for (int mf = 0; mf < 4; mf++)
                #pragma unroll
                for (int nf = 0; nf < 4; nf++) {
                    mma_bf16(acc[mf][nf], ah[mf], bh[nf]);
                    mma_bf16(acc[mf][nf], ah[mf], bl[nf]);
                    mma_bf16(acc[mf][nf], al[mf], bh[nf]);
                }
        }
        __syncthreads();
    }

    const int gid = lane >> 2, qid = lane & 3;
    #pragma unroll
    for (int mf = 0; mf < 4; mf++) {
        const int row0 = m0 + wm * 64 + mf * 16 + gid;
        #pragma unroll
        for (int nf = 0; nf < 4; nf++) {
            const int col = n0 + wn * 32 + nf * 8 + qid * 2;
            const float b0 = bias[col], b1 = bias[col + 1];
            float v00 = acc[mf][nf][0] + b0, v01 = acc[mf][nf][1] + b1;
            float v10 = acc[mf][nf][2] + b0, v11 = acc[mf][nf][3] + b1;
            if (mode == 0) {
                *(float2*)(Cf + (size_t)row0 * Ndim + col)       = make_float2(v00, v01);
                *(float2*)(Cf + (size_t)(row0 + 8) * Ndim + col) = make_float2(v10, v11);
            } else {
                uint32_t h0 = pack_bf16(v00, v01);
                uint32_t h1 = pack_bf16(v10, v11);
                uint32_t l0 = pack_bf16(v00 - __uint_as_float(h0 << 16),
                                        v01 - __uint_as_float(h0 & 0xFFFF0000u));
                uint32_t l1 = pack_bf16(v10 - __uint_as_float(h1 << 16),
                                        v11 - __uint_as_float(h1 & 0xFFFF0000u));
                *(uint32_t*)(Chi + (size_t)row0 * Ndim + col)       = h0;
                *(uint32_t*)(Chi + (size_t)(row0 + 8) * Ndim + col) = h1;
                *(uint32_t*)(Clo + (size_t)row0 * Ndim + col)       = l0;
                *(uint32_t*)(Clo + (size_t)(row0 + 8) * Ndim + col) = l1;
            }
        }
    }
}

// ---------------------------------------------------------------------------
// Flash attention on mma.sync (bf16 hi/lo, 3-term).  Br=128, Bc=64, 8 warps.
// K/V double-buffered via cp.async.  Output written as bf16 hi/lo.
// ---------------------------------------------------------------------------
#define AROW  136                    // bf16 per smem row (128 + 8 pad)
#define AROWB 272
#define AQH   0
#define AQL   34816                  // 128*272
#define ASTG0 69632
#define ASTGB 69632                  // 4 * 64*272
#define AKH   0
#define AKL   17408
#define AVH   34816
#define AVL   52224
#define ATTN_SMEM (69632 + 2 * 69632)   // 208896

__device__ __forceinline__ void attn_stage(
    uint32_t sbase, int b, int h, int kt, int t)
{
    const size_t rowbase = (size_t)(b * S_ + kt * 64);
    #pragma unroll
    for (int c = t; c < 1024; c += 256) {
        int r = c >> 4, cc = c & 15;
        uint32_t so = (uint32_t)(r * AROWB + cc * 16);
        size_t gk = (rowbase + r) * OQKV_ + H_     + h * HD_ + cc * 8;
        size_t gv = (rowbase + r) * OQKV_ + 2 * H_ + h * HD_ + cc * 8;
        cp16(sbase + AKH + so, g_qkvh + gk);
        cp16(sbase + AKL + so, g_qkvl + gk);
        cp16(sbase + AVH + so, g_qkvh + gv);
        cp16(sbase + AVL + so, g_qkvl + gv);
    }
}

__global__ __launch_bounds__(256, 1) void attn_mma()
{
    extern __shared__ char smc[];
    const uint32_t sb = smem_u32(smc);

    const int t    = threadIdx.x;
    const int lane = t & 31;
    const int wid  = t >> 5;
    const int qt   = blockIdx.x;
    const int h    = blockIdx.y;
    const int b    = blockIdx.z;

    const float C1 = 0.08838834764831844f * 1.44269504088896341f;  // scale*log2(e)

    // ---- load Q tile (128 rows x 128 cols, hi+lo) into smem
    {
        const __nv_bfloat16* qh = g_qkvh + (size_t)(b * S_ + qt * 128) * OQKV_ + h * HD_;
        const __nv_bfloat16* ql = g_qkvl + (size_t)(b * S_ + qt * 128) * OQKV_ + h * HD_;
        #pragma unroll
        for (int c = t; c < 2048; c += 256) {
            int r = c >> 4, cc = c & 15;
            uint32_t so = (uint32_t)(r * AROWB + cc * 16);
            *(uint4*)(smc + AQH + so) = *(const uint4*)(qh + (size_t)r * OQKV_ + cc * 8);
            *(uint4*)(smc + AQL + so) = *(const uint4*)(ql + (size_t)r * OQKV_ + cc * 8);
        }
    }

    float oacc[16][4];
    #pragma unroll
    for (int j = 0; j < 16; j++)
        #pragma unroll
        for (int k = 0; k < 4; k++) oacc[j][k] = 0.f;
    float mrow[2] = {-INFINITY, -INFINITY};
    float lrow[2] = {0.f, 0.f};

    attn_stage(sb + ASTG0, b, h, 0, t);
    CP_COMMIT();

    const int ra = lane & 15;
    const int ca = (lane >> 4) & 1;

    for (int kt = 0; kt < S_ / 64; kt++) {
        const int cur = kt & 1;
        const uint32_t kb = sb + ASTG0 + cur * ASTGB;

        CP_WAIT0();
        __syncthreads();                       // stage `cur` visible; prev compute done
        if (kt + 1 < S_ / 64) {
            attn_stage(sb + ASTG0 + (cur ^ 1) * ASTGB, b, h, kt + 1, t);
            CP_COMMIT();
        }

        // ---- S = Q K^T  (raw scores, fp32 accum)
        float s[8][4];
        #pragma unroll
        for (int j = 0; j < 8; j++)
            #pragma unroll
            for (int k = 0; k < 4; k++) s[j][k] = 0.f;

        #pragma unroll
        for (int ks = 0; ks < 8; ks++) {
            uint32_t qhf[4], qlf[4];
            const uint32_t aoff = (uint32_t)((wid * 16 + ra) * AROWB + (ks * 16 + ca * 8) * 2);
            ldsm_x4(qhf, sb + AQH + aoff);
            ldsm_x4(qlf, sb + AQL + aoff);
            #pragma unroll
            for (int jj = 0; jj < 4; jj++) {
                uint32_t bh4[4], bl4[4];
                const uint32_t boff = (uint32_t)(
                    (jj * 16 + ((lane >> 4) & 1) * 8 + (lane & 7)) * AROWB +
                    (ks * 16 + ((lane >> 3) & 1) * 8) * 2);
                ldsm_x4(bh4, kb + AKH + boff);
                ldsm_x4(bl4, kb + AKL + boff);
                mma_bf16(s[2 * jj],     qhf, bh4);
                mma_bf16(s[2 * jj],     qhf, bl4);
                mma_bf16(s[2 * jj],     qlf, bh4);
                mma_bf16(s[2 * jj + 1], qhf, bh4 + 2);
                mma_bf16(s[2 * jj + 1], qhf, bl4 + 2);
                mma_bf16(s[2 * jj + 1], qlf, bh4 + 2);
            }
        }

        // ---- online softmax on fragments
        float mx0 = s[0][0], mx1 = s[0][2];
        #pragma unroll
        for (int j = 0; j < 8; j++) {
            mx0 = fmaxf(mx0, fmaxf(s[j][0], s[j][1]));
            mx1 = fmaxf(mx1, fmaxf(s[j][2], s[j][3]));
        }
        mx0 = fmaxf(mx0, __shfl_xor_sync(0xFFFFFFFFu, mx0, 1));
        mx0 = fmaxf(mx0, __shfl_xor_sync(0xFFFFFFFFu, mx0, 2));
        mx1 = fmaxf(mx1, __shfl_xor_sync(0xFFFFFFFFu, mx1, 1));
        mx1 = fmaxf(mx1, __shfl_xor_sync(0xFFFFFFFFu, mx1, 2));

        const float mn0 = fmaxf(mrow[0], mx0);
        const float mn1 = fmaxf(mrow[1], mx1);
        const float corr0 = fexp2((mrow[0] - mn0) * C1);
        const float corr1 = fexp2((mrow[1] - mn1) * C1);
        const float mc0 = mn0 * C1, mc1 = mn1 * C1;
        mrow[0] = mn0; mrow[1] = mn1;

        float sum0 = 0.f, sum1 = 0.f;
        #pragma unroll
        for (int j = 0; j < 8; j++) {
            s[j][0] = fexp2(fmaf(s[j][0], C1, -mc0));
            s[j][1] = fexp2(fmaf(s[j][1], C1, -mc0));
            s[j][2] = fexp2(fmaf(s[j][2], C1, -mc1));
            s[j][3] = fexp2(fmaf(s[j][3], C1, -mc1));
            sum0 += s[j][0] + s[j][1];
            sum1 += s[j][2] + s[j][3];
        }
        sum0 += __shfl_xor_sync(0xFFFFFFFFu, sum0, 1);
        sum0 += __shfl_xor_sync(0xFFFFFFFFu, sum0, 2);
        sum1 += __shfl_xor_sync(0xFFFFFFFFu, sum1, 1);
        sum1 += __shfl_xor_sync(0xFFFFFFFFu, sum1, 2);
        lrow[0] = lrow[0] * corr0 + sum0;
        lrow[1] = lrow[1] * corr1 + sum1;

        #pragma unroll
        for (int j = 0; j < 16; j++) {
            oacc[j][0] *= corr0; oacc[j][1] *= corr0;
            oacc[j][2] *= corr1; oacc[j][3] *= corr1;
        }

        // ---- O += P V   (P split hi/lo in-register; V via ldmatrix.trans)
        #pragma unroll
        for (int kc = 0; kc < 4; kc++) {
            uint32_t pah[4], pal[4];
            #pragma unroll
            for (int u = 0; u < 2; u++) {
                const int jt = 2 * kc + u;
                uint32_t h0 = pack_bf16(s[jt][0], s[jt][1]);
                uint32_t h1 = pack_bf16(s[jt][2], s[jt][3]);
                pah[2 * u]     = h0;
                pah[2 * u + 1] = h1;
                pal[2 * u]     = pack_bf16(s[jt][0] - __uint_as_float(h0 << 16),
                                           s[jt][1] - __uint_as_float(h0 & 0xFFFF0000u));
                pal[2 * u + 1] = pack_bf16(s[jt][2] - __uint_as_float(h1 << 16),
                                           s[jt][3] - __uint_as_float(h1 & 0xFFFF0000u));
            }
            #pragma unroll
            for (int jj = 0; jj < 8; jj++) {
                uint32_t vh4[4], vl4[4];
                const uint32_t voff = (uint32_t)(
                    (kc * 16 + ((lane >> 3) & 1) * 8 + (lane & 7)) * AROWB +
                    (jj * 16 + (lane >> 4) * 8) * 2);
                ldsm_x4t(vh4, kb + AVH + voff);
                ldsm_x4t(vl4, kb + AVL + voff);
                mma_bf16(oacc[2 * jj],     pah, vh4);
                mma_bf16(oacc[2 * jj],     pah, vl4);
                mma_bf16(oacc[2 * jj],     pal, vh4);
                mma_bf16(oacc[2 * jj + 1], pah, vh4 + 2);
                mma_bf16(oacc[2 * jj + 1], pah, vl4 + 2);
                mma_bf16(oacc[2 * jj + 1], pal, vh4 + 2);
            }
        }
    }

    // ---- normalize and store as bf16 hi/lo
    const float inv0 = 1.f / lrow[0];
    const float inv1 = 1.f / lrow[1];
    const int row0 = b * S_ + qt * 128 + wid * 16 + (lane >> 2);
    #pragma unroll
    for (int j = 0; j < 16; j++) {
        const int col = h * HD_ + j * 8 + (lane & 3) * 2;
        float v00 = oacc[j][0] * inv0, v01 = oacc[j][1] * inv0;
        float v10 = oacc[j][2] * inv1, v11 = oacc[j][3] * inv1;
        uint32_t h0 = pack_bf16(v00, v01);
        uint32_t h1 = pack_bf16(v10, v11);
        uint32_t l0 = pack_bf16(v00 - __uint_as_float(h0 << 16),
                                v01 - __uint_as_float(h0 & 0xFFFF0000u));
        uint32_t l1 = pack_bf16(v10 - __uint_as_float(h1 << 16),
                                v11 - __uint_as_float(h1 & 0xFFFF0000u));
        *(uint32_t*)(g_ath + (size_t)row0 * H_ + col)       = h0;
        *(uint32_t*)(g_ath + (size_t)(row0 + 8) * H_ + col) = h1;
        *(uint32_t*)(g_atl + (size_t)row0 * H_ + col)       = l0;
        *(uint32_t*)(g_atl + (size_t)(row0 + 8) * H_ + col) = l1;
    }
}

// ---------------------------------------------------------------------------
extern "C" void kernel_launch(void* const* d_in, const int* in_sizes, int n_in,
                              void* d_out, int out_size)
{
    const float* x     = (const float*)d_in[0];
    const float* w_qkv = (const float*)d_in[1];
    const float* b_qkv = (const float*)d_in[2];
    const float* w_out = (const float*)d_in[3];
    const float* b_out = (const float*)d_in[4];
    float* out = (float*)d_out;

    __nv_bfloat16 *xh, *xl, *wqh, *wql, *woh, *wol, *qkvh, *qkvl, *ath, *atl;
    cudaGetSymbolAddress((void**)&xh,   g_xh);   cudaGetSymbolAddress((void**)&xl,   g_xl);
    cudaGetSymbolAddress((void**)&wqh,  g_wqh);  cudaGetSymbolAddress((void**)&wql,  g_wql);
    cudaGetSymbolAddress((void**)&woh,  g_woh);  cudaGetSymbolAddress((void**)&wol,  g_wol);
    cudaGetSymbolAddress((void**)&qkvh, g_qkvh); cudaGetSymbolAddress((void**)&qkvl, g_qkvl);
    cudaGetSymbolAddress((void**)&ath,  g_ath);  cudaGetSymbolAddress((void**)&atl,  g_atl);

    cudaFuncSetAttribute(gemm_mma, cudaFuncAttributeMaxDynamicSharedMemorySize, GEMM_SMEM);
    cudaFuncSetAttribute(attn_mma, cudaFuncAttributeMaxDynamicSharedMemorySize, ATTN_SMEM);

    const int nx = M_ * H_, nwq = OQKV_ * H_, nwo = H_ * H_;
    conv_hilo<<<(nx  / 4 + 255) / 256, 256>>>(x,     xh,  xl,  nx);
    conv_hilo<<<(nwq / 4 + 255) / 256, 256>>>(w_qkv, wqh, wql, nwq);
    conv_hilo<<<(nwo / 4 + 255) / 256, 256>>>(w_out, woh, wol, nwo);

    // 1) QKV projection -> bf16 hi/lo directly
    gemm_mma<<<dim3(OQKV_ / 128, M_ / 128), 256, GEMM_SMEM>>>(
        xh, xl, wqh, wql, b_qkv, nullptr, qkvh, qkvl, OQKV_, H_, 1);

    // 2) Attention (tensor cores) -> bf16 hi/lo directly
    attn_mma<<<dim3(S_ / 128, NH_, B_), 256, ATTN_SMEM>>>();

    // 3) Output projection -> fp32
    gemm_mma<<<dim3(H_ / 128, M_ / 128), 256, GEMM_SMEM>>>(
        ath, atl, woh, wol, b_out, out, nullptr, nullptr, H_, H_, 0);
}

// round 6
// speedup vs baseline: 5.5079x; 1.1037x over previous
#include <cuda_runtime.h>
#include <cuda_bf16.h>
#include <math.h>
#include <stdint.h>
#include <cstdint>
#include <cstddef>

#define B_    2
#define S_    2048
#define H_    2048
#define NH_   16
#define HD_   128
#define M_    (B_*S_)       // 4096
#define OQKV_ (3*H_)        // 6144

// ---------------------------------------------------------------------------
// Device-global scratch
// ---------------------------------------------------------------------------
__device__ __nv_bfloat16 g_xh  [(size_t)M_ * H_];
__device__ __nv_bfloat16 g_xl  [(size_t)M_ * H_];
__device__ __nv_bfloat16 g_wqh [(size_t)OQKV_ * H_];
__device__ __nv_bfloat16 g_wql [(size_t)OQKV_ * H_];
__device__ __nv_bfloat16 g_woh [(size_t)H_ * H_];
__device__ __nv_bfloat16 g_wol [(size_t)H_ * H_];
__device__ __nv_bfloat16 g_qkvh[(size_t)M_ * OQKV_];
__device__ __nv_bfloat16 g_qkvl[(size_t)M_ * OQKV_];
__device__ __nv_bfloat16 g_ath [(size_t)M_ * H_];
__device__ __nv_bfloat16 g_atl [(size_t)M_ * H_];

// ---------------------------------------------------------------------------
// helpers
// ---------------------------------------------------------------------------
__device__ __forceinline__ uint32_t smem_u32(const void* p) {
    uint32_t a;
    asm("{ .reg .u64 t; cvta.to.shared.u64 t, %1; cvt.u32.u64 %0, t; }"
        : "=r"(a) : "l"(p));
    return a;
}
__device__ __forceinline__ void ldsm_x4(uint32_t* r, uint32_t addr) {
    asm volatile("ldmatrix.sync.aligned.m8n8.x4.shared.b16 {%0,%1,%2,%3}, [%4];"
                 : "=r"(r[0]), "=r"(r[1]), "=r"(r[2]), "=r"(r[3]) : "r"(addr));
}
__device__ __forceinline__ void ldsm_x4t(uint32_t* r, uint32_t addr) {
    asm volatile("ldmatrix.sync.aligned.m8n8.x4.trans.shared.b16 {%0,%1,%2,%3}, [%4];"
                 : "=r"(r[0]), "=r"(r[1]), "=r"(r[2]), "=r"(r[3]) : "r"(addr));
}
__device__ __forceinline__ void mma_bf16(float* c, const uint32_t* a, const uint32_t* b) {
    asm volatile(
        "mma.sync.aligned.m16n8k16.row.col.f32.bf16.bf16.f32 "
        "{%0,%1,%2,%3}, {%4,%5,%6,%7}, {%8,%9}, {%0,%1,%2,%3};"
        : "+f"(c[0]), "+f"(c[1]), "+f"(c[2]), "+f"(c[3])
        : "r"(a[0]), "r"(a[1]), "r"(a[2]), "r"(a[3]), "r"(b[0]), "r"(b[1]));
}
__device__ __forceinline__ void cp16(uint32_t saddr, const void* gptr) {
    asm volatile("cp.async.cg.shared.global [%0], [%1], 16;"
                 :: "r"(saddr), "l"(__cvta_generic_to_global(gptr)));
}
#define CP_COMMIT() asm volatile("cp.async.commit_group;" ::: "memory")
#define CP_WAIT2()  asm volatile("cp.async.wait_group 2;" ::: "memory")
#define CP_WAIT1()  asm volatile("cp.async.wait_group 1;" ::: "memory")
#define CP_WAIT0()  asm volatile("cp.async.wait_group 0;" ::: "memory")

__device__ __forceinline__ uint32_t pack_bf16(float lo, float hi) {
    uint32_t r;
    asm("cvt.rn.bf16x2.f32 %0, %1, %2;" : "=r"(r) : "f"(hi), "f"(lo));
    return r;
}

// fast exp2 via degree-5 FMA polynomial
__device__ __forceinline__ float fexp2(float t) {
    t = fmaxf(t, -126.f);
    int   e = __float2int_rn(t);
    float f = t - (float)e;
    float p = 1.3333558146428443e-3f;
    p = fmaf(p, f, 9.618129107628477e-3f);
    p = fmaf(p, f, 5.550410866482158e-2f);
    p = fmaf(p, f, 2.402265069591007e-1f);
    p = fmaf(p, f, 6.931471805599453e-1f);
    p = fmaf(p, f, 1.0f);
    return p * __int_as_float((e + 127) << 23);
}

// ---------------------------------------------------------------------------
// fp32 -> bf16 hi/lo split
// ---------------------------------------------------------------------------
__global__ __launch_bounds__(256) void conv_hilo(
    const float* __restrict__ s, __nv_bfloat16* __restrict__ hi,
    __nv_bfloat16* __restrict__ lo, int n)
{
    int i = (blockIdx.x * 256 + threadIdx.x) * 4;
    if (i >= n) return;
    float4 v = *(const float4*)(s + i);
    uint32_t h01 = pack_bf16(v.x, v.y);
    uint32_t h23 = pack_bf16(v.z, v.w);
    float f0 = __uint_as_float(h01 << 16);
    float f1 = __uint_as_float(h01 & 0xFFFF0000u);
    float f2 = __uint_as_float(h23 << 16);
    float f3 = __uint_as_float(h23 & 0xFFFF0000u);
    *(uint32_t*)(hi + i)     = h01;
    *(uint32_t*)(hi + i + 2) = h23;
    *(uint32_t*)(lo + i)     = pack_bf16(v.x - f0, v.y - f1);
    *(uint32_t*)(lo + i + 2) = pack_bf16(v.z - f2, v.w - f3);
}

// ---------------------------------------------------------------------------
// mma.sync GEMM: C[M,N] = A[M,K] @ B[N,K]^T + bias  (3-term bf16 hi/lo)
// 128x128 block tile, BK=32, 8 warps, 3-stage cp.async, XOR-swizzled smem
// (64B rows, no pad), B via ldmatrix.x4.  2 CTAs/SM (96KB smem each).
// ---------------------------------------------------------------------------
#define BK     32
#define MATB   8192                  // 128 rows * 64B
#define STAGEB (4 * MATB)            // 32768
#define GEMM_SMEM (3 * STAGEB)       // 98304

// swizzled byte offset inside one matrix for (row, 16B-chunk)
__device__ __forceinline__ uint32_t swz(int row, int ch) {
    return (uint32_t)(row * 64 + ((ch ^ ((row >> 1) & 3)) * 16));
}

__device__ __forceinline__ void stage_load(
    uint32_t s0, const __nv_bfloat16* __restrict__ Ah,
    const __nv_bfloat16* __restrict__ Al,
    const __nv_bfloat16* __restrict__ Bh,
    const __nv_bfloat16* __restrict__ Bl,
    int m0, int n0, int Kdim, int kb, int t)
{
    const size_t kof = (size_t)kb * BK;
    #pragma unroll
    for (int u = 0; u < 2; u++) {
        int c   = t + u * 256;
        int row = c >> 2, ch = c & 3;
        uint32_t so = swz(row, ch);
        size_t ga = (size_t)(m0 + row) * Kdim + kof + ch * 8;
        size_t gb = (size_t)(n0 + row) * Kdim + kof + ch * 8;
        cp16(s0 + 0 * MATB + so, Ah + ga);
        cp16(s0 + 1 * MATB + so, Al + ga);
        cp16(s0 + 2 * MATB + so, Bh + gb);
        cp16(s0 + 3 * MATB + so, Bl + gb);
    }
}

__global__ __launch_bounds__(256, 2) void gemm_mma(
    const __nv_bfloat16* __restrict__ Ah, const __nv_bfloat16* __restrict__ Al,
    const __nv_bfloat16* __restrict__ Bh, const __nv_bfloat16* __restrict__ Bl,
    const float* __restrict__ bias, float* __restrict__ Cf,
    __nv_bfloat16* __restrict__ Chi, __nv_bfloat16* __restrict__ Clo,
    int Ndim, int Kdim, int mode)
{
    extern __shared__ char smc[];
    const uint32_t sb = smem_u32(smc);

    const int t    = threadIdx.x;
    const int lane = t & 31;
    const int wid  = t >> 5;
    const int wm   = wid >> 2;
    const int wn   = wid & 3;
    const int m0   = blockIdx.y * 128;
    const int n0   = blockIdx.x * 128;

    float acc[4][4][4];
    #pragma unroll
    for (int i = 0; i < 4; i++)
        #pragma unroll
        for (int j = 0; j < 4; j++)
            #pragma unroll
            for (int k = 0; k < 4; k++) acc[i][j][k] = 0.f;

    const int nkb = Kdim / BK;

    stage_load(sb,          Ah, Al, Bh, Bl, m0, n0, Kdim, 0, t);
    CP_COMMIT();
    stage_load(sb + STAGEB, Ah, Al, Bh, Bl, m0, n0, Kdim, 1, t);
    CP_COMMIT();

    const int ra  = lane & 15;               // A row-in-16
    const int ca  = (lane >> 4) & 1;         // A chunk add
    const int rbn = ((lane >> 4) & 1) * 8 + (lane & 7);  // B row add (x4, 16 rows)
    const int cbn = (lane >> 3) & 1;         // B chunk add

    for (int kb = 0; kb < nkb; kb++) {
        if (kb + 2 < nkb) {
            stage_load(sb + (uint32_t)((kb + 2) % 3) * STAGEB,
                       Ah, Al, Bh, Bl, m0, n0, Kdim, kb + 2, t);
            CP_COMMIT();
            CP_WAIT2();
        } else if (kb + 1 < nkb) {
            CP_WAIT1();
        } else {
            CP_WAIT0();
        }
        __syncthreads();

        const uint32_t s0 = sb + (uint32_t)(kb % 3) * STAGEB;
        #pragma unroll
        for (int ks = 0; ks < 2; ks++) {
            uint32_t ah[4][4], al[4][4], bh[2][4], bl[2][4];
            #pragma unroll
            for (int mf = 0; mf < 4; mf++) {
                const int arow = wm * 64 + mf * 16 + ra;
                const uint32_t aoff = swz(arow, ks * 2 + ca);
                ldsm_x4(ah[mf], s0 + 0 * MATB + aoff);
                ldsm_x4(al[mf], s0 + 1 * MATB + aoff);
            }
            #pragma unroll
            for (int nfp = 0; nfp < 2; nfp++) {
                const int brow = wn * 32 + nfp * 16 + rbn;
                const uint32_t boff = swz(brow, ks * 2 + cbn);
                ldsm_x4(bh[nfp], s0 + 2 * MATB + boff);
                ldsm_x4(bl[nfp], s0 + 3 * MATB + boff);
            }
            #pragma unroll
            for (int mf = 0; mf < 4; mf++)
                #pragma unroll
                for (int nfp = 0; nfp < 2; nfp++)
                    #pragma unroll
                    for (int sub = 0; sub < 2; sub++) {
                        float* a4 = acc[mf][nfp * 2 + sub];
                        mma_bf16(a4, ah[mf], bh[nfp] + 2 * sub);
                        mma_bf16(a4, ah[mf], bl[nfp] + 2 * sub);
                        mma_bf16(a4, al[mf], bh[nfp] + 2 * sub);
                    }
        }
        __syncthreads();
    }

    const int gid = lane >> 2, qid = lane & 3;
    #pragma unroll
    for (int mf = 0; mf < 4; mf++) {
        const int row0 = m0 + wm * 64 + mf * 16 + gid;
        #pragma unroll
        for (int nf = 0; nf < 4; nf++) {
            const int col = n0 + wn * 32 + nf * 8 + qid * 2;
            const float b0 = bias[col], b1 = bias[col + 1];
            float v00 = acc[mf][nf][0] + b0, v01 = acc[mf][nf][1] + b1;
            float v10 = acc[mf][nf][2] + b0, v11 = acc[mf][nf][3] + b1;
            if (mode == 0) {
                *(float2*)(Cf + (size_t)row0 * Ndim + col)       = make_float2(v00, v01);
                *(float2*)(Cf + (size_t)(row0 + 8) * Ndim + col) = make_float2(v10, v11);
            } else {
                uint32_t h0 = pack_bf16(v00, v01);
                uint32_t h1 = pack_bf16(v10, v11);
                uint32_t l0 = pack_bf16(v00 - __uint_as_float(h0 << 16),
                                        v01 - __uint_as_float(h0 & 0xFFFF0000u));
                uint32_t l1 = pack_bf16(v10 - __uint_as_float(h1 << 16),
                                        v11 - __uint_as_float(h1 & 0xFFFF0000u));
                *(uint32_t*)(Chi + (size_t)row0 * Ndim + col)       = h0;
                *(uint32_t*)(Chi + (size_t)(row0 + 8) * Ndim + col) = h1;
                *(uint32_t*)(Clo + (size_t)row0 * Ndim + col)       = l0;
                *(uint32_t*)(Clo + (size_t)(row0 + 8) * Ndim + col) = l1;
            }
        }
    }
}

// ---------------------------------------------------------------------------
// Flash attention on mma.sync (bf16 hi/lo, 3-term).  Br=128, Bc=64, 8 warps.
// ---------------------------------------------------------------------------
#define AROWB 272
#define AQH   0
#define AQL   34816
#define ASTG0 69632
#define ASTGB 69632
#define AKH   0
#define AKL   17408
#define AVH   34816
#define AVL   52224
#define ATTN_SMEM (69632 + 2 * 69632)

__device__ __forceinline__ void attn_stage(
    uint32_t sbase, int b, int h, int kt, int t)
{
    const size_t rowbase = (size_t)(b * S_ + kt * 64);
    #pragma unroll
    for (int c = t; c < 1024; c += 256) {
        int r = c >> 4, cc = c & 15;
        uint32_t so = (uint32_t)(r * AROWB + cc * 16);
        size_t gk = (rowbase + r) * OQKV_ + H_     + h * HD_ + cc * 8;
        size_t gv = (rowbase + r) * OQKV_ + 2 * H_ + h * HD_ + cc * 8;
        cp16(sbase + AKH + so, g_qkvh + gk);
        cp16(sbase + AKL + so, g_qkvl + gk);
        cp16(sbase + AVH + so, g_qkvh + gv);
        cp16(sbase + AVL + so, g_qkvl + gv);
    }
}

__global__ __launch_bounds__(256, 1) void attn_mma()
{
    extern __shared__ char smc[];
    const uint32_t sb = smem_u32(smc);

    const int t    = threadIdx.x;
    const int lane = t & 31;
    const int wid  = t >> 5;
    const int qt   = blockIdx.x;
    const int h    = blockIdx.y;
    const int b    = blockIdx.z;

    const float C1 = 0.08838834764831844f * 1.44269504088896341f;

    {
        const __nv_bfloat16* qh = g_qkvh + (size_t)(b * S_ + qt * 128) * OQKV_ + h * HD_;
        const __nv_bfloat16* ql = g_qkvl + (size_t)(b * S_ + qt * 128) * OQKV_ + h * HD_;
        #pragma unroll
        for (int c = t; c < 2048; c += 256) {
            int r = c >> 4, cc = c & 15;
            uint32_t so = (uint32_t)(r * AROWB + cc * 16);
            *(uint4*)(smc + AQH + so) = *(const uint4*)(qh + (size_t)r * OQKV_ + cc * 8);
            *(uint4*)(smc + AQL + so) = *(const uint4*)(ql + (size_t)r * OQKV_ + cc * 8);
        }
    }

    float oacc[16][4];
    #pragma unroll
    for (int j = 0; j < 16; j++)
        #pragma unroll
        for (int k = 0; k < 4; k++) oacc[j][k] = 0.f;
    float mrow[2] = {-INFINITY, -INFINITY};
    float lrow[2] = {0.f, 0.f};

    attn_stage(sb + ASTG0, b, h, 0, t);
    CP_COMMIT();

    const int ra = lane & 15;
    const int ca = (lane >> 4) & 1;

    for (int kt = 0; kt < S_ / 64; kt++) {
        const int cur = kt & 1;
        const uint32_t kb = sb + ASTG0 + cur * ASTGB;

        CP_WAIT0();
        __syncthreads();
        if (kt + 1 < S_ / 64) {
            attn_stage(sb + ASTG0 + (cur ^ 1) * ASTGB, b, h, kt + 1, t);
            CP_COMMIT();
        }

        float s[8][4];
        #pragma unroll
        for (int j = 0; j < 8; j++)
            #pragma unroll
            for (int k = 0; k < 4; k++) s[j][k] = 0.f;

        #pragma unroll
        for (int ks = 0; ks < 8; ks++) {
            uint32_t qhf[4], qlf[4];
            const uint32_t aoff = (uint32_t)((wid * 16 + ra) * AROWB + (ks * 16 + ca * 8) * 2);
            ldsm_x4(qhf, sb + AQH + aoff);
            ldsm_x4(qlf, sb + AQL + aoff);
            #pragma unroll
            for (int jj = 0; jj < 4; jj++) {
                uint32_t bh4[4], bl4[4];
                const uint32_t boff = (uint32_t)(
                    (jj * 16 + ((lane >> 4) & 1) * 8 + (lane & 7)) * AROWB +
                    (ks * 16 + ((lane >> 3) & 1) * 8) * 2);
                ldsm_x4(bh4, kb + AKH + boff);
                ldsm_x4(bl4, kb + AKL + boff);
                mma_bf16(s[2 * jj],     qhf, bh4);
                mma_bf16(s[2 * jj],     qhf, bl4);
                mma_bf16(s[2 * jj],     qlf, bh4);
                mma_bf16(s[2 * jj + 1], qhf, bh4 + 2);
                mma_bf16(s[2 * jj + 1], qhf, bl4 + 2);
                mma_bf16(s[2 * jj + 1], qlf, bh4 + 2);
            }
        }

        float mx0 = s[0][0], mx1 = s[0][2];
        #pragma unroll
        for (int j = 0; j < 8; j++) {
            mx0 = fmaxf(mx0, fmaxf(s[j][0], s[j][1]));
            mx1 = fmaxf(mx1, fmaxf(s[j][2], s[j][3]));
        }
        mx0 = fmaxf(mx0, __shfl_xor_sync(0xFFFFFFFFu, mx0, 1));
        mx0 = fmaxf(mx0, __shfl_xor_sync(0xFFFFFFFFu, mx0, 2));
        mx1 = fmaxf(mx1, __shfl_xor_sync(0xFFFFFFFFu, mx1, 1));
        mx1 = fmaxf(mx1, __shfl_xor_sync(0xFFFFFFFFu, mx1, 2));

        const float mn0 = fmaxf(mrow[0], mx0);
        const float mn1 = fmaxf(mrow[1], mx1);
        const float corr0 = fexp2((mrow[0] - mn0) * C1);
        const float corr1 = fexp2((mrow[1] - mn1) * C1);
        const float mc0 = mn0 * C1, mc1 = mn1 * C1;
        mrow[0] = mn0; mrow[1] = mn1;

        float sum0 = 0.f, sum1 = 0.f;
        #pragma unroll
        for (int j = 0; j < 8; j++) {
            s[j][0] = fexp2(fmaf(s[j][0], C1, -mc0));
            s[j][1] = fexp2(fmaf(s[j][1], C1, -mc0));
            s[j][2] = fexp2(fmaf(s[j][2], C1, -mc1));
            s[j][3] = fexp2(fmaf(s[j][3], C1, -mc1));
            sum0 += s[j][0] + s[j][1];
            sum1 += s[j][2] + s[j][3];
        }
        sum0 += __shfl_xor_sync(0xFFFFFFFFu, sum0, 1);
        sum0 += __shfl_xor_sync(0xFFFFFFFFu, sum0, 2);
        sum1 += __shfl_xor_sync(0xFFFFFFFFu, sum1, 1);
        sum1 += __shfl_xor_sync(0xFFFFFFFFu, sum1, 2);
        lrow[0] = lrow[0] * corr0 + sum0;
        lrow[1] = lrow[1] * corr1 + sum1;

        #pragma unroll
        for (int j = 0; j < 16; j++) {
            oacc[j][0] *= corr0; oacc[j][1] *= corr0;
            oacc[j][2] *= corr1; oacc[j][3] *= corr1;
        }

        #pragma unroll
        for (int kc = 0; kc < 4; kc++) {
            uint32_t pah[4], pal[4];
            #pragma unroll
            for (int u = 0; u < 2; u++) {
                const int jt = 2 * kc + u;
                uint32_t h0 = pack_bf16(s[jt][0], s[jt][1]);
                uint32_t h1 = pack_bf16(s[jt][2], s[jt][3]);
                pah[2 * u]     = h0;
                pah[2 * u + 1] = h1;
                pal[2 * u]     = pack_bf16(s[jt][0] - __uint_as_float(h0 << 16),
                                           s[jt][1] - __uint_as_float(h0 & 0xFFFF0000u));
                pal[2 * u + 1] = pack_bf16(s[jt][2] - __uint_as_float(h1 << 16),
                                           s[jt][3] - __uint_as_float(h1 & 0xFFFF0000u));
            }
            #pragma unroll
            for (int jj = 0; jj < 8; jj++) {
                uint32_t vh4[4], vl4[4];
                const uint32_t voff = (uint32_t)(
                    (kc * 16 + ((lane >> 3) & 1) * 8 + (lane & 7)) * AROWB +
                    (jj * 16 + (lane >> 4) * 8) * 2);
                ldsm_x4t(vh4, kb + AVH + voff);
                ldsm_x4t(vl4, kb + AVL + voff);
                mma_bf16(oacc[2 * jj],     pah, vh4);
                mma_bf16(oacc[2 * jj],     pah, vl4);
                mma_bf16(oacc[2 * jj],     pal, vh4);
                mma_bf16(oacc[2 * jj + 1], pah, vh4 + 2);
                mma_bf16(oacc[2 * jj + 1], pah, vl4 + 2);
                mma_bf16(oacc[2 * jj + 1], pal, vh4 + 2);
            }
        }
    }

    const float inv0 = 1.f / lrow[0];
    const float inv1 = 1.f / lrow[1];
    const int row0 = b * S_ + qt * 128 + wid * 16 + (lane >> 2);
    #pragma unroll
    for (int j = 0; j < 16; j++) {
        const int col = h * HD_ + j * 8 + (lane & 3) * 2;
        float v00 = oacc[j][0] * inv0, v01 = oacc[j][1] * inv0;
        float v10 = oacc[j][2] * inv1, v11 = oacc[j][3] * inv1;
        uint32_t h0 = pack_bf16(v00, v01);
        uint32_t h1 = pack_bf16(v10, v11);
        uint32_t l0 = pack_bf16(v00 - __uint_as_float(h0 << 16),
                                v01 - __uint_as_float(h0 & 0xFFFF0000u));
        uint32_t l1 = pack_bf16(v10 - __uint_as_float(h1 << 16),
                                v11 - __uint_as_float(h1 & 0xFFFF0000u));
        *(uint32_t*)(g_ath + (size_t)row0 * H_ + col)       = h0;
        *(uint32_t*)(g_ath + (size_t)(row0 + 8) * H_ + col) = h1;
        *(uint32_t*)(g_atl + (size_t)row0 * H_ + col)       = l0;
        *(uint32_t*)(g_atl + (size_t)(row0 + 8) * H_ + col) = l1;
    }
}

// ---------------------------------------------------------------------------
extern "C" void kernel_launch(void* const* d_in, const int* in_sizes, int n_in,
                              void* d_out, int out_size)
{
    const float* x     = (const float*)d_in[0];
    const float* w_qkv = (const float*)d_in[1];
    const float* b_qkv = (const float*)d_in[2];
    const float* w_out = (const float*)d_in[3];
    const float* b_out = (const float*)d_in[4];
    float* out = (float*)d_out;

    __nv_bfloat16 *xh, *xl, *wqh, *wql, *woh, *wol, *qkvh, *qkvl, *ath, *atl;
    cudaGetSymbolAddress((void**)&xh,   g_xh);   cudaGetSymbolAddress((void**)&xl,   g_xl);
    cudaGetSymbolAddress((void**)&wqh,  g_wqh);  cudaGetSymbolAddress((void**)&wql,  g_wql);
    cudaGetSymbolAddress((void**)&woh,  g_woh);  cudaGetSymbolAddress((void**)&wol,  g_wol);
    cudaGetSymbolAddress((void**)&qkvh, g_qkvh); cudaGetSymbolAddress((void**)&qkvl, g_qkvl);
    cudaGetSymbolAddress((void**)&ath,  g_ath);  cudaGetSymbolAddress((void**)&atl,  g_atl);

    cudaFuncSetAttribute(gemm_mma, cudaFuncAttributeMaxDynamicSharedMemorySize, GEMM_SMEM);
    cudaFuncSetAttribute(attn_mma, cudaFuncAttributeMaxDynamicSharedMemorySize, ATTN_SMEM);

    const int nx = M_ * H_, nwq = OQKV_ * H_, nwo = H_ * H_;
    conv_hilo<<<(nx  / 4 + 255) / 256, 256>>>(x,     xh,  xl,  nx);
    conv_hilo<<<(nwq / 4 + 255) / 256, 256>>>(w_qkv, wqh, wql, nwq);
    conv_hilo<<<(nwo / 4 + 255) / 256, 256>>>(w_out, woh, wol, nwo);

    gemm_mma<<<dim3(OQKV_ / 128, M_ / 128), 256, GEMM_SMEM>>>(
        xh, xl, wqh, wql, b_qkv, nullptr, qkvh, qkvl, OQKV_, H_, 1);

    attn_mma<<<dim3(S_ / 128, NH_, B_), 256, ATTN_SMEM>>>();

    gemm_mma<<<dim3(H_ / 128, M_ / 128), 256, GEMM_SMEM>>>(
        ath, atl, woh, wol, b_out, out, nullptr, nullptr, H_, H_, 0);
}

// round 7
// speedup vs baseline: 5.6026x; 1.0172x over previous
#include <cuda_runtime.h>
#include <cuda_bf16.h>
#include <math.h>
#include <stdint.h>
#include <cstdint>
#include <cstddef>

#define B_    2
#define S_    2048
#define H_    2048
#define NH_   16
#define HD_   128
#define M_    (B_*S_)       // 4096
#define OQKV_ (3*H_)        // 6144

// ---------------------------------------------------------------------------
// Device-global scratch
// ---------------------------------------------------------------------------
__device__ __nv_bfloat16 g_xh  [(size_t)M_ * H_];
__device__ __nv_bfloat16 g_xl  [(size_t)M_ * H_];
__device__ __nv_bfloat16 g_wqh [(size_t)OQKV_ * H_];
__device__ __nv_bfloat16 g_wql [(size_t)OQKV_ * H_];
__device__ __nv_bfloat16 g_woh [(size_t)H_ * H_];
__device__ __nv_bfloat16 g_wol [(size_t)H_ * H_];
__device__ __nv_bfloat16 g_qkvh[(size_t)M_ * OQKV_];
__device__ __nv_bfloat16 g_qkvl[(size_t)M_ * OQKV_];
__device__ __nv_bfloat16 g_ath [(size_t)M_ * H_];
__device__ __nv_bfloat16 g_atl [(size_t)M_ * H_];

// ---------------------------------------------------------------------------
// helpers
// ---------------------------------------------------------------------------
__device__ __forceinline__ uint32_t smem_u32(const void* p) {
    uint32_t a;
    asm("{ .reg .u64 t; cvta.to.shared.u64 t, %1; cvt.u32.u64 %0, t; }"
        : "=r"(a) : "l"(p));
    return a;
}
__device__ __forceinline__ void ldsm_x4(uint32_t* r, uint32_t addr) {
    asm volatile("ldmatrix.sync.aligned.m8n8.x4.shared.b16 {%0,%1,%2,%3}, [%4];"
                 : "=r"(r[0]), "=r"(r[1]), "=r"(r[2]), "=r"(r[3]) : "r"(addr));
}
__device__ __forceinline__ void ldsm_x4t(uint32_t* r, uint32_t addr) {
    asm volatile("ldmatrix.sync.aligned.m8n8.x4.trans.shared.b16 {%0,%1,%2,%3}, [%4];"
                 : "=r"(r[0]), "=r"(r[1]), "=r"(r[2]), "=r"(r[3]) : "r"(addr));
}
__device__ __forceinline__ void mma_bf16(float* c, const uint32_t* a, const uint32_t* b) {
    asm volatile(
        "mma.sync.aligned.m16n8k16.row.col.f32.bf16.bf16.f32 "
        "{%0,%1,%2,%3}, {%4,%5,%6,%7}, {%8,%9}, {%0,%1,%2,%3};"
        : "+f"(c[0]), "+f"(c[1]), "+f"(c[2]), "+f"(c[3])
        : "r"(a[0]), "r"(a[1]), "r"(a[2]), "r"(a[3]), "r"(b[0]), "r"(b[1]));
}
__device__ __forceinline__ void cp16(uint32_t saddr, const void* gptr) {
    asm volatile("cp.async.cg.shared.global [%0], [%1], 16;"
                 :: "r"(saddr), "l"(__cvta_generic_to_global(gptr)));
}
#define CP_COMMIT() asm volatile("cp.async.commit_group;" ::: "memory")
#define CP_WAIT1()  asm volatile("cp.async.wait_group 1;" ::: "memory")
#define CP_WAIT0()  asm volatile("cp.async.wait_group 0;" ::: "memory")

__device__ __forceinline__ uint32_t pack_bf16(float lo, float hi) {
    uint32_t r;
    asm("cvt.rn.bf16x2.f32 %0, %1, %2;" : "=r"(r) : "f"(hi), "f"(lo));
    return r;
}

// fast exp2 via degree-5 FMA polynomial
__device__ __forceinline__ float fexp2(float t) {
    t = fmaxf(t, -126.f);
    int   e = __float2int_rn(t);
    float f = t - (float)e;
    float p = 1.3333558146428443e-3f;
    p = fmaf(p, f, 9.618129107628477e-3f);
    p = fmaf(p, f, 5.550410866482158e-2f);
    p = fmaf(p, f, 2.402265069591007e-1f);
    p = fmaf(p, f, 6.931471805599453e-1f);
    p = fmaf(p, f, 1.0f);
    return p * __int_as_float((e + 127) << 23);
}

// ---------------------------------------------------------------------------
// fp32 -> bf16 hi/lo split
// ---------------------------------------------------------------------------
__global__ __launch_bounds__(256) void conv_hilo(
    const float* __restrict__ s, __nv_bfloat16* __restrict__ hi,
    __nv_bfloat16* __restrict__ lo, int n)
{
    int i = (blockIdx.x * 256 + threadIdx.x) * 4;
    if (i >= n) return;
    float4 v = *(const float4*)(s + i);
    uint32_t h01 = pack_bf16(v.x, v.y);
    uint32_t h23 = pack_bf16(v.z, v.w);
    float f0 = __uint_as_float(h01 << 16);
    float f1 = __uint_as_float(h01 & 0xFFFF0000u);
    float f2 = __uint_as_float(h23 << 16);
    float f3 = __uint_as_float(h23 & 0xFFFF0000u);
    *(uint32_t*)(hi + i)     = h01;
    *(uint32_t*)(hi + i + 2) = h23;
    *(uint32_t*)(lo + i)     = pack_bf16(v.x - f0, v.y - f1);
    *(uint32_t*)(lo + i + 2) = pack_bf16(v.z - f2, v.w - f3);
}

// ---------------------------------------------------------------------------
// mma.sync GEMM: C[M,N] = A[M,K] @ B[N,K]^T + bias  (3-term bf16 hi/lo)
// 128x128 block tile, BK=32, 8 warps, 3-stage cp.async, XOR-swizzled smem,
// ONE __syncthreads per K-iteration.  2 CTAs/SM.
// ---------------------------------------------------------------------------
#define BK     32
#define MATB   8192                  // 128 rows * 64B
#define STAGEB (4 * MATB)            // 32768
#define GEMM_SMEM (3 * STAGEB)       // 98304

__device__ __forceinline__ uint32_t swz(int row, int ch) {
    return (uint32_t)(row * 64 + ((ch ^ ((row >> 1) & 3)) * 16));
}

__device__ __forceinline__ void stage_load(
    uint32_t s0, const __nv_bfloat16* __restrict__ Ah,
    const __nv_bfloat16* __restrict__ Al,
    const __nv_bfloat16* __restrict__ Bh,
    const __nv_bfloat16* __restrict__ Bl,
    int m0, int n0, int Kdim, int kb, int t)
{
    const size_t kof = (size_t)kb * BK;
    #pragma unroll
    for (int u = 0; u < 2; u++) {
        int c   = t + u * 256;
        int row = c >> 2, ch = c & 3;
        uint32_t so = swz(row, ch);
        size_t ga = (size_t)(m0 + row) * Kdim + kof + ch * 8;
        size_t gb = (size_t)(n0 + row) * Kdim + kof + ch * 8;
        cp16(s0 + 0 * MATB + so, Ah + ga);
        cp16(s0 + 1 * MATB + so, Al + ga);
        cp16(s0 + 2 * MATB + so, Bh + gb);
        cp16(s0 + 3 * MATB + so, Bl + gb);
    }
}

__global__ __launch_bounds__(256, 2) void gemm_mma(
    const __nv_bfloat16* __restrict__ Ah, const __nv_bfloat16* __restrict__ Al,
    const __nv_bfloat16* __restrict__ Bh, const __nv_bfloat16* __restrict__ Bl,
    const float* __restrict__ bias, float* __restrict__ Cf,
    __nv_bfloat16* __restrict__ Chi, __nv_bfloat16* __restrict__ Clo,
    int Ndim, int Kdim, int mode)
{
    extern __shared__ char smc[];
    const uint32_t sb = smem_u32(smc);

    const int t    = threadIdx.x;
    const int lane = t & 31;
    const int wid  = t >> 5;
    const int wm   = wid >> 2;
    const int wn   = wid & 3;
    const int m0   = blockIdx.y * 128;
    const int n0   = blockIdx.x * 128;

    float acc[4][4][4];
    #pragma unroll
    for (int i = 0; i < 4; i++)
        #pragma unroll
        for (int j = 0; j < 4; j++)
            #pragma unroll
            for (int k = 0; k < 4; k++) acc[i][j][k] = 0.f;

    const int nkb = Kdim / BK;

    stage_load(sb,          Ah, Al, Bh, Bl, m0, n0, Kdim, 0, t);
    CP_COMMIT();
    stage_load(sb + STAGEB, Ah, Al, Bh, Bl, m0, n0, Kdim, 1, t);
    CP_COMMIT();

    const int ra  = lane & 15;
    const int ca  = (lane >> 4) & 1;
    const int rbn = ((lane >> 4) & 1) * 8 + (lane & 7);
    const int cbn = (lane >> 3) & 1;

    for (int kb = 0; kb < nkb; kb++) {
        if (kb + 1 < nkb) { CP_WAIT1(); } else { CP_WAIT0(); }
        __syncthreads();   // stage kb visible; all warps done with stage kb-1

        if (kb + 2 < nkb) {
            // safe: (kb+2)%3 == (kb-1)%3, released by the barrier above
            stage_load(sb + (uint32_t)((kb + 2) % 3) * STAGEB,
                       Ah, Al, Bh, Bl, m0, n0, Kdim, kb + 2, t);
            CP_COMMIT();
        }

        const uint32_t s0 = sb + (uint32_t)(kb % 3) * STAGEB;
        #pragma unroll
        for (int ks = 0; ks < 2; ks++) {
            uint32_t ah[4][4], al[4][4], bh[2][4], bl[2][4];
            #pragma unroll
            for (int mf = 0; mf < 4; mf++) {
                const int arow = wm * 64 + mf * 16 + ra;
                const uint32_t aoff = swz(arow, ks * 2 + ca);
                ldsm_x4(ah[mf], s0 + 0 * MATB + aoff);
                ldsm_x4(al[mf], s0 + 1 * MATB + aoff);
            }
            #pragma unroll
            for (int nfp = 0; nfp < 2; nfp++) {
                const int brow = wn * 32 + nfp * 16 + rbn;
                const uint32_t boff = swz(brow, ks * 2 + cbn);
                ldsm_x4(bh[nfp], s0 + 2 * MATB + boff);
                ldsm_x4(bl[nfp], s0 + 3 * MATB + boff);
            }
            #pragma unroll
            for (int mf = 0; mf < 4; mf++)
                #pragma unroll
                for (int nfp = 0; nfp < 2; nfp++)
                    #pragma unroll
                    for (int sub = 0; sub < 2; sub++) {
                        float* a4 = acc[mf][nfp * 2 + sub];
                        mma_bf16(a4, ah[mf], bh[nfp] + 2 * sub);
                        mma_bf16(a4, ah[mf], bl[nfp] + 2 * sub);
                        mma_bf16(a4, al[mf], bh[nfp] + 2 * sub);
                    }
        }
    }

    const int gid = lane >> 2, qid = lane & 3;
    #pragma unroll
    for (int mf = 0; mf < 4; mf++) {
        const int row0 = m0 + wm * 64 + mf * 16 + gid;
        #pragma unroll
        for (int nf = 0; nf < 4; nf++) {
            const int col = n0 + wn * 32 + nf * 8 + qid * 2;
            const float b0 = bias[col], b1 = bias[col + 1];
            float v00 = acc[mf][nf][0] + b0, v01 = acc[mf][nf][1] + b1;
            float v10 = acc[mf][nf][2] + b0, v11 = acc[mf][nf][3] + b1;
            if (mode == 0) {
                *(float2*)(Cf + (size_t)row0 * Ndim + col)       = make_float2(v00, v01);
                *(float2*)(Cf + (size_t)(row0 + 8) * Ndim + col) = make_float2(v10, v11);
            } else {
                uint32_t h0 = pack_bf16(v00, v01);
                uint32_t h1 = pack_bf16(v10, v11);
                uint32_t l0 = pack_bf16(v00 - __uint_as_float(h0 << 16),
                                        v01 - __uint_as_float(h0 & 0xFFFF0000u));
                uint32_t l1 = pack_bf16(v10 - __uint_as_float(h1 << 16),
                                        v11 - __uint_as_float(h1 & 0xFFFF0000u));
                *(uint32_t*)(Chi + (size_t)row0 * Ndim + col)       = h0;
                *(uint32_t*)(Chi + (size_t)(row0 + 8) * Ndim + col) = h1;
                *(uint32_t*)(Clo + (size_t)row0 * Ndim + col)       = l0;
                *(uint32_t*)(Clo + (size_t)(row0 + 8) * Ndim + col) = l1;
            }
        }
    }
}

// ---------------------------------------------------------------------------
// Flash attention on mma.sync (bf16 hi/lo, 3-term).  Br=128, Bc=64, 8 warps.
// Q fragments hoisted into registers (loaded once via ldmatrix).
// ---------------------------------------------------------------------------
#define AROWB 272
#define AQH   0
#define AQL   34816
#define ASTG0 69632
#define ASTGB 69632
#define AKH   0
#define AKL   17408
#define AVH   34816
#define AVL   52224
#define ATTN_SMEM (69632 + 2 * 69632)

__device__ __forceinline__ void attn_stage(
    uint32_t sbase, int b, int h, int kt, int t)
{
    const size_t rowbase = (size_t)(b * S_ + kt * 64);
    #pragma unroll
    for (int c = t; c < 1024; c += 256) {
        int r = c >> 4, cc = c & 15;
        uint32_t so = (uint32_t)(r * AROWB + cc * 16);
        size_t gk = (rowbase + r) * OQKV_ + H_     + h * HD_ + cc * 8;
        size_t gv = (rowbase + r) * OQKV_ + 2 * H_ + h * HD_ + cc * 8;
        cp16(sbase + AKH + so, g_qkvh + gk);
        cp16(sbase + AKL + so, g_qkvl + gk);
        cp16(sbase + AVH + so, g_qkvh + gv);
        cp16(sbase + AVL + so, g_qkvl + gv);
    }
}

__global__ __launch_bounds__(256, 1) void attn_mma()
{
    extern __shared__ char smc[];
    const uint32_t sb = smem_u32(smc);

    const int t    = threadIdx.x;
    const int lane = t & 31;
    const int wid  = t >> 5;
    const int qt   = blockIdx.x;
    const int h    = blockIdx.y;
    const int b    = blockIdx.z;

    const float C1 = 0.08838834764831844f * 1.44269504088896341f;

    {
        const __nv_bfloat16* qh = g_qkvh + (size_t)(b * S_ + qt * 128) * OQKV_ + h * HD_;
        const __nv_bfloat16* ql = g_qkvl + (size_t)(b * S_ + qt * 128) * OQKV_ + h * HD_;
        #pragma unroll
        for (int c = t; c < 2048; c += 256) {
            int r = c >> 4, cc = c & 15;
            uint32_t so = (uint32_t)(r * AROWB + cc * 16);
            *(uint4*)(smc + AQH + so) = *(const uint4*)(qh + (size_t)r * OQKV_ + cc * 8);
            *(uint4*)(smc + AQL + so) = *(const uint4*)(ql + (size_t)r * OQKV_ + cc * 8);
        }
    }

    attn_stage(sb + ASTG0, b, h, 0, t);
    CP_COMMIT();

    float oacc[16][4];
    #pragma unroll
    for (int j = 0; j < 16; j++)
        #pragma unroll
        for (int k = 0; k < 4; k++) oacc[j][k] = 0.f;
    float mrow[2] = {-INFINITY, -INFINITY};
    float lrow[2] = {0.f, 0.f};

    const int ra = lane & 15;
    const int ca = (lane >> 4) & 1;

    __syncthreads();   // Q smem visible

    // hoist Q fragments into registers (used for all 32 KV tiles)
    uint32_t qfh[8][4], qfl[8][4];
    #pragma unroll
    for (int ks = 0; ks < 8; ks++) {
        const uint32_t aoff = (uint32_t)((wid * 16 + ra) * AROWB + (ks * 16 + ca * 8) * 2);
        ldsm_x4(qfh[ks], sb + AQH + aoff);
        ldsm_x4(qfl[ks], sb + AQL + aoff);
    }

    for (int kt = 0; kt < S_ / 64; kt++) {
        const int cur = kt & 1;
        const uint32_t kb = sb + ASTG0 + cur * ASTGB;

        CP_WAIT0();
        __syncthreads();
        if (kt + 1 < S_ / 64) {
            attn_stage(sb + ASTG0 + (cur ^ 1) * ASTGB, b, h, kt + 1, t);
            CP_COMMIT();
        }

        float s[8][4];
        #pragma unroll
        for (int j = 0; j < 8; j++)
            #pragma unroll
            for (int k = 0; k < 4; k++) s[j][k] = 0.f;

        #pragma unroll
        for (int ks = 0; ks < 8; ks++) {
            #pragma unroll
            for (int jj = 0; jj < 4; jj++) {
                uint32_t bh4[4], bl4[4];
                const uint32_t boff = (uint32_t)(
                    (jj * 16 + ((lane >> 4) & 1) * 8 + (lane & 7)) * AROWB +
                    (ks * 16 + ((lane >> 3) & 1) * 8) * 2);
                ldsm_x4(bh4, kb + AKH + boff);
                ldsm_x4(bl4, kb + AKL + boff);
                mma_bf16(s[2 * jj],     qfh[ks], bh4);
                mma_bf16(s[2 * jj],     qfh[ks], bl4);
                mma_bf16(s[2 * jj],     qfl[ks], bh4);
                mma_bf16(s[2 * jj + 1], qfh[ks], bh4 + 2);
                mma_bf16(s[2 * jj + 1], qfh[ks], bl4 + 2);
                mma_bf16(s[2 * jj + 1], qfl[ks], bh4 + 2);
            }
        }

        float mx0 = s[0][0], mx1 = s[0][2];
        #pragma unroll
        for (int j = 0; j < 8; j++) {
            mx0 = fmaxf(mx0, fmaxf(s[j][0], s[j][1]));
            mx1 = fmaxf(mx1, fmaxf(s[j][2], s[j][3]));
        }
        mx0 = fmaxf(mx0, __shfl_xor_sync(0xFFFFFFFFu, mx0, 1));
        mx0 = fmaxf(mx0, __shfl_xor_sync(0xFFFFFFFFu, mx0, 2));
        mx1 = fmaxf(mx1, __shfl_xor_sync(0xFFFFFFFFu, mx1, 1));
        mx1 = fmaxf(mx1, __shfl_xor_sync(0xFFFFFFFFu, mx1, 2));

        const float mn0 = fmaxf(mrow[0], mx0);
        const float mn1 = fmaxf(mrow[1], mx1);
        const float corr0 = fexp2((mrow[0] - mn0) * C1);
        const float corr1 = fexp2((mrow[1] - mn1) * C1);
        const float mc0 = mn0 * C1, mc1 = mn1 * C1;
        mrow[0] = mn0; mrow[1] = mn1;

        float sum0 = 0.f, sum1 = 0.f;
        #pragma unroll
        for (int j = 0; j < 8; j++) {
            s[j][0] = fexp2(fmaf(s[j][0], C1, -mc0));
            s[j][1] = fexp2(fmaf(s[j][1], C1, -mc0));
            s[j][2] = fexp2(fmaf(s[j][2], C1, -mc1));
            s[j][3] = fexp2(fmaf(s[j][3], C1, -mc1));
            sum0 += s[j][0] + s[j][1];
            sum1 += s[j][2] + s[j][3];
        }
        sum0 += __shfl_xor_sync(0xFFFFFFFFu, sum0, 1);
        sum0 += __shfl_xor_sync(0xFFFFFFFFu, sum0, 2);
        sum1 += __shfl_xor_sync(0xFFFFFFFFu, sum1, 1);
        sum1 += __shfl_xor_sync(0xFFFFFFFFu, sum1, 2);
        lrow[0] = lrow[0] * corr0 + sum0;
        lrow[1] = lrow[1] * corr1 + sum1;

        #pragma unroll
        for (int j = 0; j < 16; j++) {
            oacc[j][0] *= corr0; oacc[j][1] *= corr0;
            oacc[j][2] *= corr1; oacc[j][3] *= corr1;
        }

        #pragma unroll
        for (int kc = 0; kc < 4; kc++) {
            uint32_t pah[4], pal[4];
            #pragma unroll
            for (int u = 0; u < 2; u++) {
                const int jt = 2 * kc + u;
                uint32_t h0 = pack_bf16(s[jt][0], s[jt][1]);
                uint32_t h1 = pack_bf16(s[jt][2], s[jt][3]);
                pah[2 * u]     = h0;
                pah[2 * u + 1] = h1;
                pal[2 * u]     = pack_bf16(s[jt][0] - __uint_as_float(h0 << 16),
                                           s[jt][1] - __uint_as_float(h0 & 0xFFFF0000u));
                pal[2 * u + 1] = pack_bf16(s[jt][2] - __uint_as_float(h1 << 16),
                                           s[jt][3] - __uint_as_float(h1 & 0xFFFF0000u));
            }
            #pragma unroll
            for (int jj = 0; jj < 8; jj++) {
                uint32_t vh4[4], vl4[4];
                const uint32_t voff = (uint32_t)(
                    (kc * 16 + ((lane >> 3) & 1) * 8 + (lane & 7)) * AROWB +
                    (jj * 16 + (lane >> 4) * 8) * 2);
                ldsm_x4t(vh4, kb + AVH + voff);
                ldsm_x4t(vl4, kb + AVL + voff);
                mma_bf16(oacc[2 * jj],     pah, vh4);
                mma_bf16(oacc[2 * jj],     pah, vl4);
                mma_bf16(oacc[2 * jj],     pal, vh4);
                mma_bf16(oacc[2 * jj + 1], pah, vh4 + 2);
                mma_bf16(oacc[2 * jj + 1], pah, vl4 + 2);
                mma_bf16(oacc[2 * jj + 1], pal, vh4 + 2);
            }
        }
    }

    const float inv0 = 1.f / lrow[0];
    const float inv1 = 1.f / lrow[1];
    const int row0 = b * S_ + qt * 128 + wid * 16 + (lane >> 2);
    #pragma unroll
    for (int j = 0; j < 16; j++) {
        const int col = h * HD_ + j * 8 + (lane & 3) * 2;
        float v00 = oacc[j][0] * inv0, v01 = oacc[j][1] * inv0;
        float v10 = oacc[j][2] * inv1, v11 = oacc[j][3] * inv1;
        uint32_t h0 = pack_bf16(v00, v01);
        uint32_t h1 = pack_bf16(v10, v11);
        uint32_t l0 = pack_bf16(v00 - __uint_as_float(h0 << 16),
                                v01 - __uint_as_float(h0 & 0xFFFF0000u));
        uint32_t l1 = pack_bf16(v10 - __uint_as_float(h1 << 16),
                                v11 - __uint_as_float(h1 & 0xFFFF0000u));
        *(uint32_t*)(g_ath + (size_t)row0 * H_ + col)       = h0;
        *(uint32_t*)(g_ath + (size_t)(row0 + 8) * H_ + col) = h1;
        *(uint32_t*)(g_atl + (size_t)row0 * H_ + col)       = l0;
        *(uint32_t*)(g_atl + (size_t)(row0 + 8) * H_ + col) = l1;
    }
}

// ---------------------------------------------------------------------------
extern "C" void kernel_launch(void* const* d_in, const int* in_sizes, int n_in,
                              void* d_out, int out_size)
{
    const float* x     = (const float*)d_in[0];
    const float* w_qkv = (const float*)d_in[1];
    const float* b_qkv = (const float*)d_in[2];
    const float* w_out = (const float*)d_in[3];
    const float* b_out = (const float*)d_in[4];
    float* out = (float*)d_out;

    __nv_bfloat16 *xh, *xl, *wqh, *wql, *woh, *wol, *qkvh, *qkvl, *ath, *atl;
    cudaGetSymbolAddress((void**)&xh,   g_xh);   cudaGetSymbolAddress((void**)&xl,   g_xl);
    cudaGetSymbolAddress((void**)&wqh,  g_wqh);  cudaGetSymbolAddress((void**)&wql,  g_wql);
    cudaGetSymbolAddress((void**)&woh,  g_woh);  cudaGetSymbolAddress((void**)&wol,  g_wol);
    cudaGetSymbolAddress((void**)&qkvh, g_qkvh); cudaGetSymbolAddress((void**)&qkvl, g_qkvl);
    cudaGetSymbolAddress((void**)&ath,  g_ath);  cudaGetSymbolAddress((void**)&atl,  g_atl);

    cudaFuncSetAttribute(gemm_mma, cudaFuncAttributeMaxDynamicSharedMemorySize, GEMM_SMEM);
    cudaFuncSetAttribute(attn_mma, cudaFuncAttributeMaxDynamicSharedMemorySize, ATTN_SMEM);

    const int nx = M_ * H_, nwq = OQKV_ * H_, nwo = H_ * H_;
    conv_hilo<<<(nx  / 4 + 255) / 256, 256>>>(x,     xh,  xl,  nx);
    conv_hilo<<<(nwq / 4 + 255) / 256, 256>>>(w_qkv, wqh, wql, nwq);
    conv_hilo<<<(nwo / 4 + 255) / 256, 256>>>(w_out, woh, wol, nwo);

    gemm_mma<<<dim3(OQKV_ / 128, M_ / 128), 256, GEMM_SMEM>>>(
        xh, xl, wqh, wql, b_qkv, nullptr, qkvh, qkvl, OQKV_, H_, 1);

    attn_mma<<<dim3(S_ / 128, NH_, B_), 256, ATTN_SMEM>>>();

    gemm_mma<<<dim3(H_ / 128, M_ / 128), 256, GEMM_SMEM>>>(
        ath, atl, woh, wol, b_out, out, nullptr, nullptr, H_, H_, 0);
}